// round 1
// baseline (speedup 1.0000x reference)
#include <cuda_runtime.h>
#include <math.h>

#define NN   100000
#define NE   250000
#define NB   2000
#define FIN  75
#define DIM  32
#define HID  128
#define NOUT 1024           // DIM*DIM
#define MPAD 250112         // 1954 * 128

// ---------------- scratch (static __device__, no allocation) ----------------
__device__ float g_hw[(size_t)MPAD * HID];      // edge hidden  [E,128]  (~128 MB)
__device__ float g_ew[(size_t)MPAD * NOUT];     // edge weights [E,1024] (~1.02 GB)
__device__ float g_x[NN * DIM];                 // node state
__device__ float g_acc[NN * DIM];               // conv scatter accumulator
__device__ int   g_cnt[NN];                     // in-degree
__device__ int   g_goff[NB + 1];                // graph offsets (graph_index is sorted)
__device__ float g_h2[NB * DIM];                // set2set LSTM h
__device__ float g_c2[NB * DIM];                // set2set LSTM c
__device__ float g_qstar[NB * 2 * DIM];         // set2set q_star
// transposed weights (coalesced inner loops)
__device__ float g_w0T[FIN * DIM];
__device__ float g_w1T[11 * HID];
__device__ float g_wihT[DIM * 96];
__device__ float g_whhT[DIM * 96];
__device__ float g_lwihT[64 * 128];
__device__ float g_lwhhT[DIM * 128];

// ---------------- small prep kernels ----------------
__global__ void prep_kernel(const float* __restrict__ w0, const float* __restrict__ w1,
                            const float* __restrict__ gwih, const float* __restrict__ gwhh,
                            const float* __restrict__ lwih, const float* __restrict__ lwhh) {
    int t = blockIdx.x * 256 + threadIdx.x;
    if (t < FIN * DIM) { int i = t / DIM, o = t % DIM; g_w0T[t] = w0[o * FIN + i]; }
    if (t < 11 * HID)  { int i = t / HID, j = t % HID; g_w1T[t] = w1[j * 11 + i]; }
    if (t < DIM * 96)  { int i = t / 96,  r = t % 96;  g_wihT[t] = gwih[r * DIM + i]; g_whhT[t] = gwhh[r * DIM + i]; }
    if (t < 64 * 128)  { int i = t / 128, r = t % 128; g_lwihT[t] = lwih[r * 64 + i]; }
    if (t < DIM * 128) { int i = t / 128, r = t % 128; g_lwhhT[t] = lwhh[r * DIM + i]; }
}

__global__ void zero_cnt_kernel() {
    int i = blockIdx.x * 256 + threadIdx.x;
    if (i < NN) g_cnt[i] = 0;
}
__global__ void zero_acc_kernel() {
    int i = blockIdx.x * 256 + threadIdx.x;
    if (i < NN * DIM) g_acc[i] = 0.f;
}
__global__ void zero_s2s_kernel() {
    int i = blockIdx.x * 256 + threadIdx.x;
    if (i < NB * DIM) { g_h2[i] = 0.f; g_c2[i] = 0.f; }
    if (i < NB * 2 * DIM) g_qstar[i] = 0.f;
}

__global__ void deg_kernel(const int* __restrict__ ei) {
    int e = blockIdx.x * 256 + threadIdx.x;
    if (e < NE) atomicAdd(&g_cnt[ei[NE + e]], 1);
}

// lower_bound of each graph id in the sorted graph_index
__global__ void goff_kernel(const int* __restrict__ gidx) {
    int g = blockIdx.x * 256 + threadIdx.x;
    if (g > NB) return;
    int lo = 0, hi = NN;
    while (lo < hi) { int mid = (lo + hi) >> 1; if (gidx[mid] < g) lo = mid + 1; else hi = mid; }
    g_goff[g] = lo;
}

// ---------------- lin0: x = relu(nf @ W0^T + b) ----------------
__global__ void lin0_kernel(const float* __restrict__ nf, const float* __restrict__ b) {
    int warp = threadIdx.x >> 5;
    int node = blockIdx.x * 8 + warp;
    int o = threadIdx.x & 31;
    __shared__ float sf[8][FIN + 1];
    int base = blockIdx.x * 8;
    for (int idx = threadIdx.x; idx < 8 * FIN; idx += 256) {
        int nn = base + idx / FIN;
        sf[idx / FIN][idx % FIN] = (nn < NN) ? nf[(size_t)nn * FIN + idx % FIN] : 0.f;
    }
    __syncthreads();
    if (node >= NN) return;
    float acc = b[o];
#pragma unroll
    for (int i = 0; i < FIN; i++) acc = fmaf(sf[warp][i], g_w0T[i * DIM + o], acc);
    g_x[node * DIM + o] = fmaxf(acc, 0.f);
}

// ---------------- edge hidden: hw = relu(ef @ W1^T + b1) ----------------
__global__ void hw_kernel(const float* __restrict__ ef, const float* __restrict__ b1) {
    int half = threadIdx.x >> 7;           // 2 edges per 256-thread block
    int e = blockIdx.x * 2 + half;
    int j = threadIdx.x & 127;
    __shared__ float sef[2][12];
    if (threadIdx.x < 22) {
        int le = threadIdx.x / 11, i = threadIdx.x % 11;
        int ee = blockIdx.x * 2 + le;
        sef[le][i] = (ee < NE) ? ef[(size_t)ee * 11 + i] : 0.f;
    }
    __syncthreads();
    if (e >= NE) return;
    float acc = b1[j];
#pragma unroll
    for (int i = 0; i < 11; i++) acc = fmaf(sef[half][i], g_w1T[i * HID + j], acc);
    g_hw[(size_t)e * HID + j] = fmaxf(acc, 0.f);
}

// ---------------- edge_w GEMM: C[M,1024] = HW[M,128] @ W2[1024,128]^T + b2 ----------------
// BM=128, BN=64, BK=32, 256 threads, 8x4 micro-tiles.
__global__ void gemm_ew_kernel(const float* __restrict__ B, const float* __restrict__ b2) {
    __shared__ __align__(16) float As[32][128 + 4];
    __shared__ __align__(16) float Bs[32][64 + 4];
    int bm = blockIdx.y * 128;   // y = M tiles (x-fast schedule reuses A tile across N)
    int bn = blockIdx.x * 64;
    int tid = threadIdx.x;
    int tr = tid >> 4;           // [0,16) rows of 8
    int tc = tid & 15;           // [0,16) cols of 4
    float acc[8][4];
#pragma unroll
    for (int i = 0; i < 8; i++)
#pragma unroll
        for (int j = 0; j < 4; j++) acc[i][j] = 0.f;

    for (int kk = 0; kk < 128; kk += 32) {
#pragma unroll
        for (int l = 0; l < 4; l++) {              // A tile: 128x32
            int idx = tid + l * 256;               // [0,1024)
            int m = idx >> 3, k4 = idx & 7;
            float4 v = *(const float4*)&g_hw[(size_t)(bm + m) * HID + kk + k4 * 4];
            As[k4 * 4 + 0][m] = v.x; As[k4 * 4 + 1][m] = v.y;
            As[k4 * 4 + 2][m] = v.z; As[k4 * 4 + 3][m] = v.w;
        }
#pragma unroll
        for (int l = 0; l < 2; l++) {              // B tile: 64x32
            int idx = tid + l * 256;               // [0,512)
            int n = idx >> 3, k4 = idx & 7;
            float4 v = *(const float4*)&B[(size_t)(bn + n) * HID + kk + k4 * 4];
            Bs[k4 * 4 + 0][n] = v.x; Bs[k4 * 4 + 1][n] = v.y;
            Bs[k4 * 4 + 2][n] = v.z; Bs[k4 * 4 + 3][n] = v.w;
        }
        __syncthreads();
#pragma unroll
        for (int k = 0; k < 32; k++) {
            float4 a0 = *(const float4*)&As[k][tr * 8];
            float4 a1 = *(const float4*)&As[k][tr * 8 + 4];
            float4 b0 = *(const float4*)&Bs[k][tc * 4];
            float a[8] = {a0.x, a0.y, a0.z, a0.w, a1.x, a1.y, a1.z, a1.w};
            float bb[4] = {b0.x, b0.y, b0.z, b0.w};
#pragma unroll
            for (int i = 0; i < 8; i++)
#pragma unroll
                for (int j = 0; j < 4; j++) acc[i][j] = fmaf(a[i], bb[j], acc[i][j]);
        }
        __syncthreads();
    }
    int n0 = bn + tc * 4;
    float4 bias = *(const float4*)&b2[n0];
#pragma unroll
    for (int i = 0; i < 8; i++) {
        int m = bm + tr * 8 + i;
        float4 v = make_float4(acc[i][0] + bias.x, acc[i][1] + bias.y,
                               acc[i][2] + bias.z, acc[i][3] + bias.w);
        *(float4*)&g_ew[(size_t)m * NOUT + n0] = v;
    }
}

// ---------------- NNConv: warp per edge, lane = output channel ----------------
__global__ void conv_kernel(const int* __restrict__ ei) {
    int e = blockIdx.x * 8 + (threadIdx.x >> 5);
    if (e >= NE) return;
    int o = threadIdx.x & 31;
    int src = ei[e];
    int dst = ei[NE + e];
    const float* __restrict__ w = g_ew + (size_t)e * NOUT;
    float xv = g_x[src * DIM + o];
    float s = 0.f;
#pragma unroll
    for (int i = 0; i < DIM; i++) {
        float xi = __shfl_sync(0xffffffffu, xv, i);
        s = fmaf(xi, w[i * DIM + o], s);
    }
    atomicAdd(&g_acc[dst * DIM + o], s);
}

// ---------------- scatter-mean + relu + GRU (in-place on g_x) ----------------
__global__ void gru_kernel(const float* __restrict__ cbias, const float* __restrict__ bih,
                           const float* __restrict__ bhh) {
    int warp = threadIdx.x >> 5;
    int node = blockIdx.x * 8 + warp;
    int o = threadIdx.x & 31;
    __shared__ float sm[8][DIM], sh[8][DIM];
    if (node < NN) {
        int c = g_cnt[node]; if (c < 1) c = 1;
        sm[warp][o] = fmaxf(g_acc[node * DIM + o] / (float)c + cbias[o], 0.f);
        sh[warp][o] = g_x[node * DIM + o];
    }
    __syncthreads();
    if (node >= NN) return;
    float gir = bih[o], giz = bih[DIM + o], gin = bih[2 * DIM + o];
    float ghr = bhh[o], ghz = bhh[DIM + o], ghn = bhh[2 * DIM + o];
#pragma unroll
    for (int i = 0; i < DIM; i++) {
        float mi = sm[warp][i], hi = sh[warp][i];
        gir = fmaf(mi, g_wihT[i * 96 + o], gir);
        giz = fmaf(mi, g_wihT[i * 96 + DIM + o], giz);
        gin = fmaf(mi, g_wihT[i * 96 + 2 * DIM + o], gin);
        ghr = fmaf(hi, g_whhT[i * 96 + o], ghr);
        ghz = fmaf(hi, g_whhT[i * 96 + DIM + o], ghz);
        ghn = fmaf(hi, g_whhT[i * 96 + 2 * DIM + o], ghn);
    }
    float r = 1.f / (1.f + expf(-(gir + ghr)));
    float z = 1.f / (1.f + expf(-(giz + ghz)));
    float nv = tanhf(gin + r * ghn);
    g_x[node * DIM + o] = (1.f - z) * nv + z * sh[warp][o];
}

// ---------------- Set2Set LSTM cell ----------------
__global__ void lstm_kernel(const float* __restrict__ bih, const float* __restrict__ bhh) {
    int warp = threadIdx.x >> 5;
    int b = blockIdx.x * 8 + warp;
    int o = threadIdx.x & 31;
    __shared__ float sq[8][64], shh[8][DIM];
    if (b < NB) {
        sq[warp][o]       = g_qstar[b * 64 + o];
        sq[warp][32 + o]  = g_qstar[b * 64 + 32 + o];
        shh[warp][o]      = g_h2[b * DIM + o];
    }
    __syncthreads();
    if (b >= NB) return;
    float gi = bih[o] + bhh[o];
    float gf = bih[32 + o] + bhh[32 + o];
    float gg = bih[64 + o] + bhh[64 + o];
    float go = bih[96 + o] + bhh[96 + o];
#pragma unroll
    for (int i = 0; i < 64; i++) {
        float v = sq[warp][i];
        gi = fmaf(v, g_lwihT[i * 128 + o], gi);
        gf = fmaf(v, g_lwihT[i * 128 + 32 + o], gf);
        gg = fmaf(v, g_lwihT[i * 128 + 64 + o], gg);
        go = fmaf(v, g_lwihT[i * 128 + 96 + o], go);
    }
#pragma unroll
    for (int i = 0; i < DIM; i++) {
        float v = shh[warp][i];
        gi = fmaf(v, g_lwhhT[i * 128 + o], gi);
        gf = fmaf(v, g_lwhhT[i * 128 + 32 + o], gf);
        gg = fmaf(v, g_lwhhT[i * 128 + 64 + o], gg);
        go = fmaf(v, g_lwhhT[i * 128 + 96 + o], go);
    }
    float si = 1.f / (1.f + expf(-gi));
    float sf = 1.f / (1.f + expf(-gf));
    float so = 1.f / (1.f + expf(-go));
    float cc = sf * g_c2[b * DIM + o] + si * tanhf(gg);
    g_c2[b * DIM + o] = cc;
    g_h2[b * DIM + o] = so * tanhf(cc);
}

// ---------------- Set2Set attention: one block per graph (nodes contiguous) ----------------
__global__ void attn_kernel() {
    int g = blockIdx.x;
    int s = g_goff[g], e = g_goff[g + 1];
    int lane = threadIdx.x & 31, w = threadIdx.x >> 5;
    __shared__ float q[DIM];
    __shared__ float red[4];
    __shared__ float sr[4][DIM];
    __shared__ float sd[4];
    if (threadIdx.x < DIM) q[threadIdx.x] = g_h2[g * DIM + threadIdx.x];
    __syncthreads();
    // pass 1: per-graph max of e_n = <x_n, q>
    float mx = -INFINITY;
    for (int n = s + w; n < e; n += 4) {
        float v = g_x[n * DIM + lane] * q[lane];
#pragma unroll
        for (int off = 16; off; off >>= 1) v += __shfl_xor_sync(0xffffffffu, v, off);
        mx = fmaxf(mx, v);
    }
    if (lane == 0) red[w] = mx;
    __syncthreads();
    mx = fmaxf(fmaxf(red[0], red[1]), fmaxf(red[2], red[3]));
    // pass 2: accumulate sum(exp) and sum(exp * x) -> divide once at end
    float denom = 0.f, racc = 0.f;
    for (int n = s + w; n < e; n += 4) {
        float xo = g_x[n * DIM + lane];
        float v = xo * q[lane];
#pragma unroll
        for (int off = 16; off; off >>= 1) v += __shfl_xor_sync(0xffffffffu, v, off);
        float ex = __expf(v - mx);
        denom += ex;
        racc = fmaf(ex, xo, racc);
    }
    sr[w][lane] = racc;
    if (lane == 0) sd[w] = denom;
    __syncthreads();
    if (w == 0) {
        float r = sr[0][lane] + sr[1][lane] + sr[2][lane] + sr[3][lane];
        float d = sd[0] + sd[1] + sd[2] + sd[3];
        r = (d > 0.f) ? r / d : 0.f;
        g_qstar[g * 64 + lane] = q[lane];
        g_qstar[g * 64 + 32 + lane] = r;
    }
}

// ---------------- writeout: [pooled (2000x64), out (100000x32)] ----------------
__global__ void writeout_kernel(float* __restrict__ out) {
    int i = blockIdx.x * 256 + threadIdx.x;
    if (i >= NB * 64 + NN * DIM) return;
    out[i] = (i < NB * 64) ? g_qstar[i] : g_x[i - NB * 64];
}

// ---------------- launch ----------------
extern "C" void kernel_launch(void* const* d_in, const int* in_sizes, int n_in,
                              void* d_out, int out_size) {
    const float* nf        = (const float*)d_in[0];
    const float* ef        = (const float*)d_in[1];
    const float* lin0_w    = (const float*)d_in[2];
    const float* lin0_b    = (const float*)d_in[3];
    const float* nn_w1     = (const float*)d_in[4];
    const float* nn_b1     = (const float*)d_in[5];
    const float* nn_w2     = (const float*)d_in[6];
    const float* nn_b2     = (const float*)d_in[7];
    const float* conv_bias = (const float*)d_in[8];
    const float* gru_wih   = (const float*)d_in[9];
    const float* gru_whh   = (const float*)d_in[10];
    const float* gru_bih   = (const float*)d_in[11];
    const float* gru_bhh   = (const float*)d_in[12];
    const float* lstm_wih  = (const float*)d_in[13];
    const float* lstm_whh  = (const float*)d_in[14];
    const float* lstm_bih  = (const float*)d_in[15];
    const float* lstm_bhh  = (const float*)d_in[16];
    const int*   ei        = (const int*)d_in[17];
    const int*   gidx      = (const int*)d_in[18];

    prep_kernel<<<32, 256>>>(lin0_w, nn_w1, gru_wih, gru_whh, lstm_wih, lstm_whh);
    zero_cnt_kernel<<<(NN + 255) / 256, 256>>>();
    deg_kernel<<<(NE + 255) / 256, 256>>>(ei);
    goff_kernel<<<8, 256>>>(gidx);
    lin0_kernel<<<NN / 8, 256>>>(nf, lin0_b);
    hw_kernel<<<NE / 2, 256>>>(ef, nn_b1);
    gemm_ew_kernel<<<dim3(NOUT / 64, MPAD / 128), 256>>>(nn_w2, nn_b2);

    for (int t = 0; t < 3; t++) {
        zero_acc_kernel<<<(NN * DIM + 255) / 256, 256>>>();
        conv_kernel<<<NE / 8, 256>>>(ei);
        gru_kernel<<<NN / 8, 256>>>(conv_bias, gru_bih, gru_bhh);
    }

    zero_s2s_kernel<<<(NB * 2 * DIM + 255) / 256, 256>>>();
    for (int s = 0; s < 3; s++) {
        lstm_kernel<<<NB / 8, 256>>>(lstm_bih, lstm_bhh);
        attn_kernel<<<NB, 128>>>();
    }
    writeout_kernel<<<(NB * 64 + NN * DIM + 255) / 256, 256>>>((float*)d_out);
}

// round 4
// speedup vs baseline: 2.1740x; 2.1740x over previous
#include <cuda_runtime.h>
#include <cuda_fp16.h>
#include <math.h>
#include <stdint.h>

#define NN   100000
#define NE   250000
#define NB   2000
#define FIN  75
#define DIM  32
#define HID  128
#define NOUT 1024           // DIM*DIM
#define MPAD 250112         // 1954 * 128

// ---------------- scratch (static __device__, no allocation) ----------------
__device__ __align__(16) __half g_hwb[(size_t)MPAD * HID];   // edge hidden fp16 (~64 MB)
__device__ __align__(16) __half g_ewb[(size_t)MPAD * NOUT];  // edge weights fp16 (~512 MB)
__device__ __align__(16) __half g_w2b[NOUT * HID];           // W2 fp16
__device__ float g_x[NN * DIM];                 // node state
__device__ float g_acc[NN * DIM];               // conv scatter accumulator
__device__ int   g_cnt[NN];                     // in-degree
__device__ int   g_goff[NB + 1];                // graph offsets (graph_index is sorted)
__device__ float g_h2[NB * DIM];                // set2set LSTM h
__device__ float g_c2[NB * DIM];                // set2set LSTM c
__device__ float g_qstar[NB * 2 * DIM];         // set2set q_star
// transposed weights (coalesced inner loops)
__device__ float g_w0T[FIN * DIM];
__device__ float g_w1T[11 * HID];
__device__ float g_wihT[DIM * 96];
__device__ float g_whhT[DIM * 96];
__device__ float g_lwihT[64 * 128];
__device__ float g_lwhhT[DIM * 128];

__device__ __forceinline__ uint32_t smem_u32(const void* p) {
    uint32_t a;
    asm("{ .reg .u64 t; cvta.to.shared.u64 t, %1; cvt.u32.u64 %0, t; }" : "=r"(a) : "l"(p));
    return a;
}

// ---------------- small prep kernels ----------------
__global__ void prep_kernel(const float* __restrict__ w0, const float* __restrict__ w1,
                            const float* __restrict__ gwih, const float* __restrict__ gwhh,
                            const float* __restrict__ lwih, const float* __restrict__ lwhh,
                            const float* __restrict__ w2) {
    int t = blockIdx.x * 256 + threadIdx.x;
    if (t < FIN * DIM) { int i = t / DIM, o = t % DIM; g_w0T[t] = w0[o * FIN + i]; }
    if (t < 11 * HID)  { int i = t / HID, j = t % HID; g_w1T[t] = w1[j * 11 + i]; }
    if (t < DIM * 96)  { int i = t / 96,  r = t % 96;  g_wihT[t] = gwih[r * DIM + i]; g_whhT[t] = gwhh[r * DIM + i]; }
    if (t < 64 * 128)  { int i = t / 128, r = t % 128; g_lwihT[t] = lwih[r * 64 + i]; }
    if (t < DIM * 128) { int i = t / 128, r = t % 128; g_lwhhT[t] = lwhh[r * DIM + i]; }
    if (t < NOUT * HID) g_w2b[t] = __float2half(w2[t]);
}

__global__ void zero_cnt_kernel() {
    int i = blockIdx.x * 256 + threadIdx.x;
    if (i < NN) g_cnt[i] = 0;
}
__global__ void zero_acc_kernel() {
    int i = blockIdx.x * 256 + threadIdx.x;
    if (i < NN * DIM) g_acc[i] = 0.f;
}
__global__ void zero_s2s_kernel() {
    int i = blockIdx.x * 256 + threadIdx.x;
    if (i < NB * DIM) { g_h2[i] = 0.f; g_c2[i] = 0.f; }
    if (i < NB * 2 * DIM) g_qstar[i] = 0.f;
}

__global__ void deg_kernel(const int* __restrict__ ei) {
    int e = blockIdx.x * 256 + threadIdx.x;
    if (e < NE) atomicAdd(&g_cnt[ei[NE + e]], 1);
}

__global__ void goff_kernel(const int* __restrict__ gidx) {
    int g = blockIdx.x * 256 + threadIdx.x;
    if (g > NB) return;
    int lo = 0, hi = NN;
    while (lo < hi) { int mid = (lo + hi) >> 1; if (gidx[mid] < g) lo = mid + 1; else hi = mid; }
    g_goff[g] = lo;
}

// ---------------- lin0: x = relu(nf @ W0^T + b) ----------------
__global__ void lin0_kernel(const float* __restrict__ nf, const float* __restrict__ b) {
    int warp = threadIdx.x >> 5;
    int node = blockIdx.x * 8 + warp;
    int o = threadIdx.x & 31;
    __shared__ float sf[8][FIN + 1];
    int base = blockIdx.x * 8;
    for (int idx = threadIdx.x; idx < 8 * FIN; idx += 256) {
        int nn = base + idx / FIN;
        sf[idx / FIN][idx % FIN] = (nn < NN) ? nf[(size_t)nn * FIN + idx % FIN] : 0.f;
    }
    __syncthreads();
    if (node >= NN) return;
    float acc = b[o];
#pragma unroll
    for (int i = 0; i < FIN; i++) acc = fmaf(sf[warp][i], g_w0T[i * DIM + o], acc);
    g_x[node * DIM + o] = fmaxf(acc, 0.f);
}

// ---------------- edge hidden: hwb = fp16(relu(ef @ W1^T + b1)), zero-pad to MPAD ----------------
__global__ void hw_kernel(const float* __restrict__ ef, const float* __restrict__ b1) {
    int half_ = threadIdx.x >> 7;
    int e = blockIdx.x * 2 + half_;
    int j = threadIdx.x & 127;
    __shared__ float sef[2][12];
    if (threadIdx.x < 22) {
        int le = threadIdx.x / 11, i = threadIdx.x % 11;
        int ee = blockIdx.x * 2 + le;
        sef[le][i] = (ee < NE) ? ef[(size_t)ee * 11 + i] : 0.f;
    }
    __syncthreads();
    if (e >= MPAD) return;
    if (e >= NE) { g_hwb[(size_t)e * HID + j] = __float2half(0.f); return; }
    float acc = b1[j];
#pragma unroll
    for (int i = 0; i < 11; i++) acc = fmaf(sef[half_][i], g_w1T[i * HID + j], acc);
    g_hwb[(size_t)e * HID + j] = __float2half(fmaxf(acc, 0.f));
}

// ---------------- HMMA GEMM: ewb[M,1024] = hwb[M,128] @ W2b[1024,128]^T + b2 ----------------
// Per CTA: M=128, N=128, K=128. 8 warps (4 M x 2 N), warp tile 32x64, mma m16n8k16 fp16.
// SMEM xor-swizzle (chunk ^= row&7 within 128B halves) -> conflict-free ldmatrix.
#define CSTRIDE 272
#define SMEM_GEMM_TOTAL (65536 + 512)

__device__ __forceinline__ void mma_fp16(float* c, const uint32_t* a, uint32_t b0, uint32_t b1) {
    asm volatile(
        "mma.sync.aligned.m16n8k16.row.col.f32.f16.f16.f32 "
        "{%0,%1,%2,%3}, {%4,%5,%6,%7}, {%8,%9}, {%0,%1,%2,%3};"
        : "+f"(c[0]), "+f"(c[1]), "+f"(c[2]), "+f"(c[3])
        : "r"(a[0]), "r"(a[1]), "r"(a[2]), "r"(a[3]), "r"(b0), "r"(b1));
}

__global__ void __launch_bounds__(256) gemm_mma_kernel(const float* __restrict__ b2) {
    extern __shared__ __align__(16) char smem[];
    uint32_t sbase = smem_u32(smem);
    float* sbias = (float*)(smem + 65536);
    int tid = threadIdx.x, lane = tid & 31, wid = tid >> 5;
    int bm = blockIdx.y * 128, bn = blockIdx.x * 128;

    if (tid < 128) sbias[tid] = b2[bn + tid];

    // load A tile [128 x 128 fp16], 16 chunks (16B) per row, xor swizzle
    const uint4* gA = (const uint4*)(g_hwb + (size_t)bm * HID);
#pragma unroll
    for (int it = 0; it < 8; it++) {
        int idx = tid + it * 256;
        int row = idx >> 4, c = idx & 15;
        uint4 v = gA[idx];
        int cs = (c & 8) | ((c ^ row) & 7);
        *(uint4*)(smem + row * 256 + cs * 16) = v;
    }
    // load B tile [128 x 128 fp16]
    const uint4* gB = (const uint4*)(g_w2b + (size_t)bn * HID);
#pragma unroll
    for (int it = 0; it < 8; it++) {
        int idx = tid + it * 256;
        int row = idx >> 4, c = idx & 15;
        uint4 v = gB[idx];
        int cs = (c & 8) | ((c ^ row) & 7);
        *(uint4*)(smem + 32768 + row * 256 + cs * 16) = v;
    }
    __syncthreads();

    int wm = (wid & 3) * 32;     // warp M base (local)
    int wn = (wid >> 2) * 64;    // warp N base (local)
    float acc[2][8][4];
#pragma unroll
    for (int mb = 0; mb < 2; mb++)
#pragma unroll
        for (int nb = 0; nb < 8; nb++)
#pragma unroll
            for (int q = 0; q < 4; q++) acc[mb][nb][q] = 0.f;

#pragma unroll
    for (int ks = 0; ks < 8; ks++) {
        int ck0 = ks * 2;
        uint32_t a[2][4], b[4][4];
#pragma unroll
        for (int mb = 0; mb < 2; mb++) {
            int row = wm + mb * 16 + (lane & 7) + ((lane >> 3) & 1) * 8;
            int ck = ck0 + (lane >> 4);
            int cs = (ck & 8) | ((ck ^ row) & 7);
            uint32_t addr = sbase + row * 256 + cs * 16;
            asm volatile("ldmatrix.sync.aligned.m8n8.x4.shared.b16 {%0,%1,%2,%3}, [%4];"
                         : "=r"(a[mb][0]), "=r"(a[mb][1]), "=r"(a[mb][2]), "=r"(a[mb][3])
                         : "r"(addr));
        }
#pragma unroll
        for (int nb4 = 0; nb4 < 4; nb4++) {
            int t = lane >> 3, r = lane & 7;
            int n = wn + nb4 * 16 + r + (t >> 1) * 8;
            int ck = ck0 + (t & 1);
            int cs = (ck & 8) | ((ck ^ n) & 7);
            uint32_t addr = sbase + 32768 + n * 256 + cs * 16;
            asm volatile("ldmatrix.sync.aligned.m8n8.x4.shared.b16 {%0,%1,%2,%3}, [%4];"
                         : "=r"(b[nb4][0]), "=r"(b[nb4][1]), "=r"(b[nb4][2]), "=r"(b[nb4][3])
                         : "r"(addr));
        }
#pragma unroll
        for (int mb = 0; mb < 2; mb++)
#pragma unroll
            for (int nb = 0; nb < 8; nb++)
                mma_fp16(acc[mb][nb], a[mb], b[nb >> 1][(nb & 1) * 2], b[nb >> 1][(nb & 1) * 2 + 1]);
    }

    __syncthreads();   // done reading A/B tiles; reuse smem for C staging (stride 272B)

    int g = lane >> 2, tg = lane & 3;
#pragma unroll
    for (int mb = 0; mb < 2; mb++)
#pragma unroll
        for (int nb = 0; nb < 8; nb++) {
            int rowl = wm + mb * 16 + g;
            int nl = wn + nb * 8 + tg * 2;
            float b0 = sbias[nl], b1 = sbias[nl + 1];
            float* c = acc[mb][nb];
            __half2 p0 = __floats2half2_rn(c[0] + b0, c[1] + b1);
            __half2 p1 = __floats2half2_rn(c[2] + b0, c[3] + b1);
            *(uint32_t*)(smem + rowl * CSTRIDE + nl * 2) = *(uint32_t*)&p0;
            *(uint32_t*)(smem + (rowl + 8) * CSTRIDE + nl * 2) = *(uint32_t*)&p1;
        }
    __syncthreads();

    __half* dst = g_ewb + (size_t)bm * NOUT + bn;
#pragma unroll
    for (int it = 0; it < 8; it++) {
        int idx = tid + it * 256;
        int row = idx >> 4, c = idx & 15;
        uint4 v = *(const uint4*)(smem + row * CSTRIDE + c * 16);
        *(uint4*)(dst + (size_t)row * NOUT + c * 8) = v;
    }
}

// ---------------- NNConv: warp per edge, lane = output channel (fp16 weights) ----------------
__global__ void conv_kernel(const int* __restrict__ ei) {
    int e = blockIdx.x * 8 + (threadIdx.x >> 5);
    if (e >= NE) return;
    int o = threadIdx.x & 31;
    int src = ei[e];
    int dst = ei[NE + e];
    const __half* __restrict__ w = g_ewb + (size_t)e * NOUT;
    float xv = g_x[src * DIM + o];
    float s = 0.f;
#pragma unroll
    for (int i = 0; i < DIM; i++) {
        float xi = __shfl_sync(0xffffffffu, xv, i);
        s = fmaf(xi, __half2float(w[i * DIM + o]), s);
    }
    atomicAdd(&g_acc[dst * DIM + o], s);
}

// ---------------- scatter-mean + relu + GRU (in-place on g_x) ----------------
__global__ void gru_kernel(const float* __restrict__ cbias, const float* __restrict__ bih,
                           const float* __restrict__ bhh) {
    int warp = threadIdx.x >> 5;
    int node = blockIdx.x * 8 + warp;
    int o = threadIdx.x & 31;
    __shared__ float sm[8][DIM], sh[8][DIM];
    if (node < NN) {
        int c = g_cnt[node]; if (c < 1) c = 1;
        sm[warp][o] = fmaxf(g_acc[node * DIM + o] / (float)c + cbias[o], 0.f);
        sh[warp][o] = g_x[node * DIM + o];
    }
    __syncthreads();
    if (node >= NN) return;
    float gir = bih[o], giz = bih[DIM + o], gin = bih[2 * DIM + o];
    float ghr = bhh[o], ghz = bhh[DIM + o], ghn = bhh[2 * DIM + o];
#pragma unroll
    for (int i = 0; i < DIM; i++) {
        float mi = sm[warp][i], hi = sh[warp][i];
        gir = fmaf(mi, g_wihT[i * 96 + o], gir);
        giz = fmaf(mi, g_wihT[i * 96 + DIM + o], giz);
        gin = fmaf(mi, g_wihT[i * 96 + 2 * DIM + o], gin);
        ghr = fmaf(hi, g_whhT[i * 96 + o], ghr);
        ghz = fmaf(hi, g_whhT[i * 96 + DIM + o], ghz);
        ghn = fmaf(hi, g_whhT[i * 96 + 2 * DIM + o], ghn);
    }
    float r = 1.f / (1.f + expf(-(gir + ghr)));
    float z = 1.f / (1.f + expf(-(giz + ghz)));
    float nv = tanhf(gin + r * ghn);
    g_x[node * DIM + o] = (1.f - z) * nv + z * sh[warp][o];
}

// ---------------- Set2Set LSTM cell ----------------
__global__ void lstm_kernel(const float* __restrict__ bih, const float* __restrict__ bhh) {
    int warp = threadIdx.x >> 5;
    int b = blockIdx.x * 8 + warp;
    int o = threadIdx.x & 31;
    __shared__ float sq[8][64], shh[8][DIM];
    if (b < NB) {
        sq[warp][o]       = g_qstar[b * 64 + o];
        sq[warp][32 + o]  = g_qstar[b * 64 + 32 + o];
        shh[warp][o]      = g_h2[b * DIM + o];
    }
    __syncthreads();
    if (b >= NB) return;
    float gi = bih[o] + bhh[o];
    float gf = bih[32 + o] + bhh[32 + o];
    float gg = bih[64 + o] + bhh[64 + o];
    float go = bih[96 + o] + bhh[96 + o];
#pragma unroll
    for (int i = 0; i < 64; i++) {
        float v = sq[warp][i];
        gi = fmaf(v, g_lwihT[i * 128 + o], gi);
        gf = fmaf(v, g_lwihT[i * 128 + 32 + o], gf);
        gg = fmaf(v, g_lwihT[i * 128 + 64 + o], gg);
        go = fmaf(v, g_lwihT[i * 128 + 96 + o], go);
    }
#pragma unroll
    for (int i = 0; i < DIM; i++) {
        float v = shh[warp][i];
        gi = fmaf(v, g_lwhhT[i * 128 + o], gi);
        gf = fmaf(v, g_lwhhT[i * 128 + 32 + o], gf);
        gg = fmaf(v, g_lwhhT[i * 128 + 64 + o], gg);
        go = fmaf(v, g_lwhhT[i * 128 + 96 + o], go);
    }
    float si = 1.f / (1.f + expf(-gi));
    float sf = 1.f / (1.f + expf(-gf));
    float so = 1.f / (1.f + expf(-go));
    float cc = sf * g_c2[b * DIM + o] + si * tanhf(gg);
    g_c2[b * DIM + o] = cc;
    g_h2[b * DIM + o] = so * tanhf(cc);
}

// ---------------- Set2Set attention: one block per graph ----------------
__global__ void attn_kernel() {
    int g = blockIdx.x;
    int s = g_goff[g], e = g_goff[g + 1];
    int lane = threadIdx.x & 31, w = threadIdx.x >> 5;
    __shared__ float q[DIM];
    __shared__ float red[4];
    __shared__ float sr[4][DIM];
    __shared__ float sd[4];
    if (threadIdx.x < DIM) q[threadIdx.x] = g_h2[g * DIM + threadIdx.x];
    __syncthreads();
    float mx = -INFINITY;
    for (int n = s + w; n < e; n += 4) {
        float v = g_x[n * DIM + lane] * q[lane];
#pragma unroll
        for (int off = 16; off; off >>= 1) v += __shfl_xor_sync(0xffffffffu, v, off);
        mx = fmaxf(mx, v);
    }
    if (lane == 0) red[w] = mx;
    __syncthreads();
    mx = fmaxf(fmaxf(red[0], red[1]), fmaxf(red[2], red[3]));
    float denom = 0.f, racc = 0.f;
    for (int n = s + w; n < e; n += 4) {
        float xo = g_x[n * DIM + lane];
        float v = xo * q[lane];
#pragma unroll
        for (int off = 16; off; off >>= 1) v += __shfl_xor_sync(0xffffffffu, v, off);
        float ex = __expf(v - mx);
        denom += ex;
        racc = fmaf(ex, xo, racc);
    }
    sr[w][lane] = racc;
    if (lane == 0) sd[w] = denom;
    __syncthreads();
    if (w == 0) {
        float r = sr[0][lane] + sr[1][lane] + sr[2][lane] + sr[3][lane];
        float d = sd[0] + sd[1] + sd[2] + sd[3];
        r = (d > 0.f) ? r / d : 0.f;
        g_qstar[g * 64 + lane] = q[lane];
        g_qstar[g * 64 + 32 + lane] = r;
    }
}

// ---------------- writeout: [pooled (2000x64), out (100000x32)] ----------------
__global__ void writeout_kernel(float* __restrict__ out) {
    int i = blockIdx.x * 256 + threadIdx.x;
    if (i >= NB * 64 + NN * DIM) return;
    out[i] = (i < NB * 64) ? g_qstar[i] : g_x[i - NB * 64];
}

// ---------------- launch ----------------
extern "C" void kernel_launch(void* const* d_in, const int* in_sizes, int n_in,
                              void* d_out, int out_size) {
    const float* nf        = (const float*)d_in[0];
    const float* ef        = (const float*)d_in[1];
    const float* lin0_w    = (const float*)d_in[2];
    const float* lin0_b    = (const float*)d_in[3];
    const float* nn_w1     = (const float*)d_in[4];
    const float* nn_b1     = (const float*)d_in[5];
    const float* nn_w2     = (const float*)d_in[6];
    const float* nn_b2     = (const float*)d_in[7];
    const float* conv_bias = (const float*)d_in[8];
    const float* gru_wih   = (const float*)d_in[9];
    const float* gru_whh   = (const float*)d_in[10];
    const float* gru_bih   = (const float*)d_in[11];
    const float* gru_bhh   = (const float*)d_in[12];
    const float* lstm_wih  = (const float*)d_in[13];
    const float* lstm_whh  = (const float*)d_in[14];
    const float* lstm_bih  = (const float*)d_in[15];
    const float* lstm_bhh  = (const float*)d_in[16];
    const int*   ei        = (const int*)d_in[17];
    const int*   gidx      = (const int*)d_in[18];

    static int smem_set = 0;
    if (!smem_set) {
        cudaFuncSetAttribute(gemm_mma_kernel, cudaFuncAttributeMaxDynamicSharedMemorySize,
                             SMEM_GEMM_TOTAL);
        smem_set = 1;
    }

    prep_kernel<<<512, 256>>>(lin0_w, nn_w1, gru_wih, gru_whh, lstm_wih, lstm_whh, nn_w2);
    zero_cnt_kernel<<<(NN + 255) / 256, 256>>>();
    deg_kernel<<<(NE + 255) / 256, 256>>>(ei);
    goff_kernel<<<8, 256>>>(gidx);
    lin0_kernel<<<NN / 8, 256>>>(nf, lin0_b);
    hw_kernel<<<MPAD / 2, 256>>>(ef, nn_b1);
    gemm_mma_kernel<<<dim3(NOUT / 128, MPAD / 128), 256, SMEM_GEMM_TOTAL>>>(nn_b2);

    for (int t = 0; t < 3; t++) {
        zero_acc_kernel<<<(NN * DIM + 255) / 256, 256>>>();
        conv_kernel<<<NE / 8, 256>>>(ei);
        gru_kernel<<<NN / 8, 256>>>(conv_bias, gru_bih, gru_bhh);
    }

    zero_s2s_kernel<<<(NB * 2 * DIM + 255) / 256, 256>>>();
    for (int s = 0; s < 3; s++) {
        lstm_kernel<<<NB / 8, 256>>>(lstm_bih, lstm_bhh);
        attn_kernel<<<NB, 128>>>();
    }
    writeout_kernel<<<(NB * 64 + NN * DIM + 255) / 256, 256>>>((float*)d_out);
}

// round 5
// speedup vs baseline: 2.3158x; 1.0652x over previous
#include <cuda_runtime.h>
#include <cuda_fp16.h>
#include <math.h>
#include <stdint.h>

#define NN   100000
#define NE   250000
#define NB   2000
#define FIN  75
#define DIM  32
#define HID  128
#define NOUT 1024           // DIM*DIM
#define MPAD 250112         // 1954 * 128

// ---------------- scratch (static __device__, no allocation) ----------------
__device__ __align__(16) __half g_ewb[(size_t)MPAD * NOUT];  // edge weights fp16 (~512 MB)
__device__ __align__(16) __half g_w2b[NOUT * HID];           // W2 fp16
__device__ float g_x[NN * DIM];                 // node state
__device__ float g_acc[NN * DIM];               // conv scatter accumulator
__device__ int   g_cnt[NN];                     // in-degree
__device__ int   g_goff[NB + 1];                // graph offsets (graph_index is sorted)
__device__ float g_h2[NB * DIM];                // set2set LSTM h
__device__ float g_c2[NB * DIM];                // set2set LSTM c
__device__ float g_qstar[NB * 2 * DIM];         // set2set q_star
// transposed weights (coalesced inner loops)
__device__ float g_w0T[FIN * DIM];
__device__ float g_w1T[11 * HID];
__device__ float g_wihT[DIM * 96];
__device__ float g_whhT[DIM * 96];
__device__ float g_lwihT[64 * 128];
__device__ float g_lwhhT[DIM * 128];

__device__ __forceinline__ uint32_t smem_u32(const void* p) {
    uint32_t a;
    asm("{ .reg .u64 t; cvta.to.shared.u64 t, %1; cvt.u32.u64 %0, t; }" : "=r"(a) : "l"(p));
    return a;
}

// ---------------- small prep kernels ----------------
__global__ void prep_kernel(const float* __restrict__ w0, const float* __restrict__ w1,
                            const float* __restrict__ gwih, const float* __restrict__ gwhh,
                            const float* __restrict__ lwih, const float* __restrict__ lwhh,
                            const float* __restrict__ w2) {
    int t = blockIdx.x * 256 + threadIdx.x;
    if (t < FIN * DIM) { int i = t / DIM, o = t % DIM; g_w0T[t] = w0[o * FIN + i]; }
    if (t < 11 * HID)  { int i = t / HID, j = t % HID; g_w1T[t] = w1[j * 11 + i]; }
    if (t < DIM * 96)  { int i = t / 96,  r = t % 96;  g_wihT[t] = gwih[r * DIM + i]; g_whhT[t] = gwhh[r * DIM + i]; }
    if (t < 64 * 128)  { int i = t / 128, r = t % 128; g_lwihT[t] = lwih[r * 64 + i]; }
    if (t < DIM * 128) { int i = t / 128, r = t % 128; g_lwhhT[t] = lwhh[r * DIM + i]; }
    if (t < NOUT * HID) g_w2b[t] = __float2half(w2[t]);
}

__global__ void zero_cnt_kernel() {
    int i = blockIdx.x * 256 + threadIdx.x;
    if (i < NN) g_cnt[i] = 0;
}
__global__ void zero_acc_kernel() {
    int i = blockIdx.x * 256 + threadIdx.x;
    if (i < NN * DIM) g_acc[i] = 0.f;
}
__global__ void zero_s2s_kernel() {
    int i = blockIdx.x * 256 + threadIdx.x;
    if (i < NB * DIM) { g_h2[i] = 0.f; g_c2[i] = 0.f; }
    if (i < NB * 2 * DIM) g_qstar[i] = 0.f;
}

__global__ void deg_kernel(const int* __restrict__ ei) {
    int e = blockIdx.x * 256 + threadIdx.x;
    if (e < NE) atomicAdd(&g_cnt[ei[NE + e]], 1);
}

__global__ void goff_kernel(const int* __restrict__ gidx) {
    int g = blockIdx.x * 256 + threadIdx.x;
    if (g > NB) return;
    int lo = 0, hi = NN;
    while (lo < hi) { int mid = (lo + hi) >> 1; if (gidx[mid] < g) lo = mid + 1; else hi = mid; }
    g_goff[g] = lo;
}

// ---------------- lin0: x = relu(nf @ W0^T + b) ----------------
__global__ void lin0_kernel(const float* __restrict__ nf, const float* __restrict__ b) {
    int warp = threadIdx.x >> 5;
    int node = blockIdx.x * 8 + warp;
    int o = threadIdx.x & 31;
    __shared__ float sf[8][FIN + 1];
    int base = blockIdx.x * 8;
    for (int idx = threadIdx.x; idx < 8 * FIN; idx += 256) {
        int nn = base + idx / FIN;
        sf[idx / FIN][idx % FIN] = (nn < NN) ? nf[(size_t)nn * FIN + idx % FIN] : 0.f;
    }
    __syncthreads();
    if (node >= NN) return;
    float acc = b[o];
#pragma unroll
    for (int i = 0; i < FIN; i++) acc = fmaf(sf[warp][i], g_w0T[i * DIM + o], acc);
    g_x[node * DIM + o] = fmaxf(acc, 0.f);
}

// ---- fused GEMM: per CTA of 128 edges ----
// prologue: hw = relu(ef @ W1^T + b1)  -> swizzled fp16 A tile in smem (persistent)
// loop nb=0..7: load B tile (g_w2b rows nb*128..), HMMA, stage C, write ewb columns
#define SM_A     0
#define SM_B     32768
#define SM_CSTG  65536           // 128 x 272B staging; prologue scratch overlaps here
#define SM_SEF   65536           // 128 x 12 floats = 6144
#define SM_W1T   (65536 + 6144)  // 11 x 128 floats = 5632
#define SM_B1    (65536 + 6144 + 5632) // 128 floats
#define SM_BIAS  100352          // 1024 floats
#define SMEM_GEMM_TOTAL 104448
#define CSTRIDE 272

__device__ __forceinline__ void mma_fp16(float* c, const uint32_t* a, uint32_t b0, uint32_t b1) {
    asm volatile(
        "mma.sync.aligned.m16n8k16.row.col.f32.f16.f16.f32 "
        "{%0,%1,%2,%3}, {%4,%5,%6,%7}, {%8,%9}, {%0,%1,%2,%3};"
        : "+f"(c[0]), "+f"(c[1]), "+f"(c[2]), "+f"(c[3])
        : "r"(a[0]), "r"(a[1]), "r"(a[2]), "r"(a[3]), "r"(b0), "r"(b1));
}

__global__ void __launch_bounds__(256) gemm_fused_kernel(const float* __restrict__ ef,
                                                         const float* __restrict__ b1,
                                                         const float* __restrict__ b2) {
    extern __shared__ __align__(16) char smem[];
    uint32_t sbase = smem_u32(smem);
    float* sef   = (float*)(smem + SM_SEF);
    float* sw1t  = (float*)(smem + SM_W1T);
    float* sb1   = (float*)(smem + SM_B1);
    float* sbias = (float*)(smem + SM_BIAS);
    int tid = threadIdx.x, lane = tid & 31, wid = tid >> 5;
    int e0 = blockIdx.x * 128;

    // ---- prologue loads ----
    for (int idx = tid; idx < 128 * 11; idx += 256) {
        int r = idx / 11, i = idx % 11;
        int e = e0 + r;
        sef[r * 12 + i] = (e < NE) ? ef[(size_t)e * 11 + i] : 0.f;
    }
    for (int idx = tid; idx < 11 * HID; idx += 256) sw1t[idx] = g_w1T[idx];
    if (tid < 128) sb1[tid] = b1[tid];
#pragma unroll
    for (int l = 0; l < 4; l++) sbias[tid + l * 256] = b2[tid + l * 256];
    __syncthreads();

    // ---- build A tile: hw = relu(ef @ W1^T + b1), fp16, xor-swizzled ----
#pragma unroll
    for (int ci = 0; ci < 8; ci++) {
        int cidx = tid + ci * 256;          // [0, 2048)
        int row = cidx >> 4, c = cidx & 15;
        int k0 = c * 8;
        float v[8];
#pragma unroll
        for (int j = 0; j < 8; j++) v[j] = sb1[k0 + j];
#pragma unroll
        for (int i = 0; i < 11; i++) {
            float e_ = sef[row * 12 + i];
#pragma unroll
            for (int j = 0; j < 8; j++) v[j] = fmaf(e_, sw1t[i * HID + k0 + j], v[j]);
        }
        uint32_t p[4];
#pragma unroll
        for (int j = 0; j < 4; j++) {
            __half2 h = __floats2half2_rn(fmaxf(v[2 * j], 0.f), fmaxf(v[2 * j + 1], 0.f));
            p[j] = *(uint32_t*)&h;
        }
        int cs = (c & 8) | ((c ^ row) & 7);
        *(uint4*)(smem + SM_A + row * 256 + cs * 16) = make_uint4(p[0], p[1], p[2], p[3]);
    }
    __syncthreads();

    int wm = (wid & 3) * 32;     // warp M base
    int wn = (wid >> 2) * 64;    // warp N base

    for (int nb = 0; nb < 8; nb++) {
        // load B tile [128 x 128 fp16]
        const uint4* gB = (const uint4*)(g_w2b + (size_t)(nb * 128) * HID);
#pragma unroll
        for (int it = 0; it < 8; it++) {
            int idx = tid + it * 256;
            int row = idx >> 4, c = idx & 15;
            uint4 v = gB[idx];
            int cs = (c & 8) | ((c ^ row) & 7);
            *(uint4*)(smem + SM_B + row * 256 + cs * 16) = v;
        }
        __syncthreads();

        float acc[2][8][4];
#pragma unroll
        for (int mb = 0; mb < 2; mb++)
#pragma unroll
            for (int nbb = 0; nbb < 8; nbb++)
#pragma unroll
                for (int q = 0; q < 4; q++) acc[mb][nbb][q] = 0.f;

#pragma unroll
        for (int ks = 0; ks < 8; ks++) {
            int ck0 = ks * 2;
            uint32_t a[2][4], b[4][4];
#pragma unroll
            for (int mb = 0; mb < 2; mb++) {
                int row = wm + mb * 16 + (lane & 7) + ((lane >> 3) & 1) * 8;
                int ck = ck0 + (lane >> 4);
                int cs = (ck & 8) | ((ck ^ row) & 7);
                uint32_t addr = sbase + SM_A + row * 256 + cs * 16;
                asm volatile("ldmatrix.sync.aligned.m8n8.x4.shared.b16 {%0,%1,%2,%3}, [%4];"
                             : "=r"(a[mb][0]), "=r"(a[mb][1]), "=r"(a[mb][2]), "=r"(a[mb][3])
                             : "r"(addr));
            }
#pragma unroll
            for (int nb4 = 0; nb4 < 4; nb4++) {
                int t = lane >> 3, r = lane & 7;
                int n = wn + nb4 * 16 + r + (t >> 1) * 8;
                int ck = ck0 + (t & 1);
                int cs = (ck & 8) | ((ck ^ n) & 7);
                uint32_t addr = sbase + SM_B + n * 256 + cs * 16;
                asm volatile("ldmatrix.sync.aligned.m8n8.x4.shared.b16 {%0,%1,%2,%3}, [%4];"
                             : "=r"(b[nb4][0]), "=r"(b[nb4][1]), "=r"(b[nb4][2]), "=r"(b[nb4][3])
                             : "r"(addr));
            }
#pragma unroll
            for (int mb = 0; mb < 2; mb++)
#pragma unroll
                for (int nbb = 0; nbb < 8; nbb++)
                    mma_fp16(acc[mb][nbb], a[mb], b[nbb >> 1][(nbb & 1) * 2], b[nbb >> 1][(nbb & 1) * 2 + 1]);
        }
        __syncthreads();   // B reads done; staging reads from prev nb done (program order)

        // stage C (fp16 + bias) at stride 272
        int g = lane >> 2, tg = lane & 3;
#pragma unroll
        for (int mb = 0; mb < 2; mb++)
#pragma unroll
            for (int nbb = 0; nbb < 8; nbb++) {
                int rowl = wm + mb * 16 + g;
                int nl = wn + nbb * 8 + tg * 2;
                float bb0 = sbias[nb * 128 + nl], bb1 = sbias[nb * 128 + nl + 1];
                float* c = acc[mb][nbb];
                __half2 p0 = __floats2half2_rn(c[0] + bb0, c[1] + bb1);
                __half2 p1 = __floats2half2_rn(c[2] + bb0, c[3] + bb1);
                *(uint32_t*)(smem + SM_CSTG + rowl * CSTRIDE + nl * 2) = *(uint32_t*)&p0;
                *(uint32_t*)(smem + SM_CSTG + (rowl + 8) * CSTRIDE + nl * 2) = *(uint32_t*)&p1;
            }
        __syncthreads();

        // coalesced write of this 128-column slab
        __half* dst = g_ewb + (size_t)e0 * NOUT + nb * 128;
#pragma unroll
        for (int it = 0; it < 8; it++) {
            int idx = tid + it * 256;
            int row = idx >> 4, c = idx & 15;
            uint4 v = *(const uint4*)(smem + SM_CSTG + row * CSTRIDE + c * 16);
            *(uint4*)(dst + (size_t)row * NOUT + c * 8) = v;
        }
        __syncthreads();
    }
}

// ---------------- NNConv: warp per edge, lane = output channel (fp16 weights) ----------------
__global__ void conv_kernel(const int* __restrict__ ei) {
    int e = blockIdx.x * 8 + (threadIdx.x >> 5);
    if (e >= NE) return;
    int o = threadIdx.x & 31;
    int src = ei[e];
    int dst = ei[NE + e];
    const __half* __restrict__ w = g_ewb + (size_t)e * NOUT;
    float xv = g_x[src * DIM + o];
    float s = 0.f;
#pragma unroll
    for (int i = 0; i < DIM; i++) {
        float xi = __shfl_sync(0xffffffffu, xv, i);
        s = fmaf(xi, __half2float(w[i * DIM + o]), s);
    }
    atomicAdd(&g_acc[dst * DIM + o], s);
}

// ---------------- scatter-mean + relu + GRU (in-place on g_x) ----------------
__global__ void gru_kernel(const float* __restrict__ cbias, const float* __restrict__ bih,
                           const float* __restrict__ bhh) {
    int warp = threadIdx.x >> 5;
    int node = blockIdx.x * 8 + warp;
    int o = threadIdx.x & 31;
    __shared__ float sm[8][DIM], sh[8][DIM];
    if (node < NN) {
        int c = g_cnt[node]; if (c < 1) c = 1;
        sm[warp][o] = fmaxf(g_acc[node * DIM + o] / (float)c + cbias[o], 0.f);
        sh[warp][o] = g_x[node * DIM + o];
    }
    __syncthreads();
    if (node >= NN) return;
    float gir = bih[o], giz = bih[DIM + o], gin = bih[2 * DIM + o];
    float ghr = bhh[o], ghz = bhh[DIM + o], ghn = bhh[2 * DIM + o];
#pragma unroll
    for (int i = 0; i < DIM; i++) {
        float mi = sm[warp][i], hi = sh[warp][i];
        gir = fmaf(mi, g_wihT[i * 96 + o], gir);
        giz = fmaf(mi, g_wihT[i * 96 + DIM + o], giz);
        gin = fmaf(mi, g_wihT[i * 96 + 2 * DIM + o], gin);
        ghr = fmaf(hi, g_whhT[i * 96 + o], ghr);
        ghz = fmaf(hi, g_whhT[i * 96 + DIM + o], ghz);
        ghn = fmaf(hi, g_whhT[i * 96 + 2 * DIM + o], ghn);
    }
    float r = 1.f / (1.f + expf(-(gir + ghr)));
    float z = 1.f / (1.f + expf(-(giz + ghz)));
    float nv = tanhf(gin + r * ghn);
    g_x[node * DIM + o] = (1.f - z) * nv + z * sh[warp][o];
}

// ---------------- Set2Set LSTM cell ----------------
__global__ void lstm_kernel(const float* __restrict__ bih, const float* __restrict__ bhh) {
    int warp = threadIdx.x >> 5;
    int b = blockIdx.x * 8 + warp;
    int o = threadIdx.x & 31;
    __shared__ float sq[8][64], shh[8][DIM];
    if (b < NB) {
        sq[warp][o]       = g_qstar[b * 64 + o];
        sq[warp][32 + o]  = g_qstar[b * 64 + 32 + o];
        shh[warp][o]      = g_h2[b * DIM + o];
    }
    __syncthreads();
    if (b >= NB) return;
    float gi = bih[o] + bhh[o];
    float gf = bih[32 + o] + bhh[32 + o];
    float gg = bih[64 + o] + bhh[64 + o];
    float go = bih[96 + o] + bhh[96 + o];
#pragma unroll
    for (int i = 0; i < 64; i++) {
        float v = sq[warp][i];
        gi = fmaf(v, g_lwihT[i * 128 + o], gi);
        gf = fmaf(v, g_lwihT[i * 128 + 32 + o], gf);
        gg = fmaf(v, g_lwihT[i * 128 + 64 + o], gg);
        go = fmaf(v, g_lwihT[i * 128 + 96 + o], go);
    }
#pragma unroll
    for (int i = 0; i < DIM; i++) {
        float v = shh[warp][i];
        gi = fmaf(v, g_lwhhT[i * 128 + o], gi);
        gf = fmaf(v, g_lwhhT[i * 128 + 32 + o], gf);
        gg = fmaf(v, g_lwhhT[i * 128 + 64 + o], gg);
        go = fmaf(v, g_lwhhT[i * 128 + 96 + o], go);
    }
    float si = 1.f / (1.f + expf(-gi));
    float sf = 1.f / (1.f + expf(-gf));
    float so = 1.f / (1.f + expf(-go));
    float cc = sf * g_c2[b * DIM + o] + si * tanhf(gg);
    g_c2[b * DIM + o] = cc;
    g_h2[b * DIM + o] = so * tanhf(cc);
}

// ---------------- Set2Set attention: one block per graph ----------------
__global__ void attn_kernel() {
    int g = blockIdx.x;
    int s = g_goff[g], e = g_goff[g + 1];
    int lane = threadIdx.x & 31, w = threadIdx.x >> 5;
    __shared__ float q[DIM];
    __shared__ float red[4];
    __shared__ float sr[4][DIM];
    __shared__ float sd[4];
    if (threadIdx.x < DIM) q[threadIdx.x] = g_h2[g * DIM + threadIdx.x];
    __syncthreads();
    float mx = -INFINITY;
    for (int n = s + w; n < e; n += 4) {
        float v = g_x[n * DIM + lane] * q[lane];
#pragma unroll
        for (int off = 16; off; off >>= 1) v += __shfl_xor_sync(0xffffffffu, v, off);
        mx = fmaxf(mx, v);
    }
    if (lane == 0) red[w] = mx;
    __syncthreads();
    mx = fmaxf(fmaxf(red[0], red[1]), fmaxf(red[2], red[3]));
    float denom = 0.f, racc = 0.f;
    for (int n = s + w; n < e; n += 4) {
        float xo = g_x[n * DIM + lane];
        float v = xo * q[lane];
#pragma unroll
        for (int off = 16; off; off >>= 1) v += __shfl_xor_sync(0xffffffffu, v, off);
        float ex = __expf(v - mx);
        denom += ex;
        racc = fmaf(ex, xo, racc);
    }
    sr[w][lane] = racc;
    if (lane == 0) sd[w] = denom;
    __syncthreads();
    if (w == 0) {
        float r = sr[0][lane] + sr[1][lane] + sr[2][lane] + sr[3][lane];
        float d = sd[0] + sd[1] + sd[2] + sd[3];
        r = (d > 0.f) ? r / d : 0.f;
        g_qstar[g * 64 + lane] = q[lane];
        g_qstar[g * 64 + 32 + lane] = r;
    }
}

// ---------------- writeout: [pooled (2000x64), out (100000x32)] ----------------
__global__ void writeout_kernel(float* __restrict__ out) {
    int i = blockIdx.x * 256 + threadIdx.x;
    if (i >= NB * 64 + NN * DIM) return;
    out[i] = (i < NB * 64) ? g_qstar[i] : g_x[i - NB * 64];
}

// ---------------- launch ----------------
extern "C" void kernel_launch(void* const* d_in, const int* in_sizes, int n_in,
                              void* d_out, int out_size) {
    const float* nf        = (const float*)d_in[0];
    const float* ef        = (const float*)d_in[1];
    const float* lin0_w    = (const float*)d_in[2];
    const float* lin0_b    = (const float*)d_in[3];
    const float* nn_w1     = (const float*)d_in[4];
    const float* nn_b1     = (const float*)d_in[5];
    const float* nn_w2     = (const float*)d_in[6];
    const float* nn_b2     = (const float*)d_in[7];
    const float* conv_bias = (const float*)d_in[8];
    const float* gru_wih   = (const float*)d_in[9];
    const float* gru_whh   = (const float*)d_in[10];
    const float* gru_bih   = (const float*)d_in[11];
    const float* gru_bhh   = (const float*)d_in[12];
    const float* lstm_wih  = (const float*)d_in[13];
    const float* lstm_whh  = (const float*)d_in[14];
    const float* lstm_bih  = (const float*)d_in[15];
    const float* lstm_bhh  = (const float*)d_in[16];
    const int*   ei        = (const int*)d_in[17];
    const int*   gidx      = (const int*)d_in[18];

    static int smem_set = 0;
    if (!smem_set) {
        cudaFuncSetAttribute(gemm_fused_kernel, cudaFuncAttributeMaxDynamicSharedMemorySize,
                             SMEM_GEMM_TOTAL);
        smem_set = 1;
    }

    prep_kernel<<<512, 256>>>(lin0_w, nn_w1, gru_wih, gru_whh, lstm_wih, lstm_whh, nn_w2);
    zero_cnt_kernel<<<(NN + 255) / 256, 256>>>();
    deg_kernel<<<(NE + 255) / 256, 256>>>(ei);
    goff_kernel<<<8, 256>>>(gidx);
    lin0_kernel<<<NN / 8, 256>>>(nf, lin0_b);
    gemm_fused_kernel<<<MPAD / 128, 256, SMEM_GEMM_TOTAL>>>(ef, nn_b1, nn_b2);

    for (int t = 0; t < 3; t++) {
        zero_acc_kernel<<<(NN * DIM + 255) / 256, 256>>>();
        conv_kernel<<<NE / 8, 256>>>(ei);
        gru_kernel<<<NN / 8, 256>>>(conv_bias, gru_bih, gru_bhh);
    }

    zero_s2s_kernel<<<(NB * 2 * DIM + 255) / 256, 256>>>();
    for (int s = 0; s < 3; s++) {
        lstm_kernel<<<NB / 8, 256>>>(lstm_bih, lstm_bhh);
        attn_kernel<<<NB, 128>>>();
    }
    writeout_kernel<<<(NB * 64 + NN * DIM + 255) / 256, 256>>>((float*)d_out);
}

// round 6
// speedup vs baseline: 2.3179x; 1.0009x over previous
#include <cuda_runtime.h>
#include <cuda_fp16.h>
#include <math.h>
#include <stdint.h>

#define NN   100000
#define NE   250000
#define NB   2000
#define FIN  75
#define DIM  32
#define HID  128
#define NOUT 1024           // DIM*DIM
#define MPAD 250112         // 1954 * 128
#define NBLK 391            // ceil(NN/256)

// ---------------- scratch (static __device__, no allocation) ----------------
__device__ __align__(16) __half g_ewb[(size_t)MPAD * NOUT];  // edge weights fp16, CSR slot order, [o][i] per edge
__device__ __align__(16) __half g_w2b[NOUT * HID];           // W2 fp16, column-permuted (c' = o*32+i)
__device__ float g_b2p[NOUT];                                // b2 permuted
__device__ float g_xa[NN * DIM];                // node state buffer A
__device__ float g_xb[NN * DIM];                // node state buffer B
__device__ int   g_cnt[NN];                     // in-degree / scatter counter
__device__ int   g_roff[NN + 1];                // CSR row offsets (by dst)
__device__ int   g_perm[MPAD];                  // slot -> original edge (-1 pad)
__device__ int   g_psrc[NE];                    // slot -> src node
__device__ int   g_bsum[NBLK];                  // scan partials
__device__ int   g_bscan[NBLK];
__device__ int   g_goff[NB + 1];                // graph offsets (graph_index is sorted)
__device__ float g_h2[NB * DIM];                // set2set LSTM h
__device__ float g_c2[NB * DIM];                // set2set LSTM c
__device__ float g_qstar[NB * 2 * DIM];         // set2set q_star
// transposed weights
__device__ float g_w0T[FIN * DIM];
__device__ float g_w1T[11 * HID];
__device__ float g_wihT[DIM * 96];
__device__ float g_whhT[DIM * 96];
__device__ float g_lwihT[64 * 128];
__device__ float g_lwhhT[DIM * 128];

__device__ __forceinline__ uint32_t smem_u32(const void* p) {
    uint32_t a;
    asm("{ .reg .u64 t; cvta.to.shared.u64 t, %1; cvt.u32.u64 %0, t; }" : "=r"(a) : "l"(p));
    return a;
}

// ---------------- prep: transposes + fp16 W2 with column permutation ----------------
__global__ void prep_kernel(const float* __restrict__ w0, const float* __restrict__ w1,
                            const float* __restrict__ gwih, const float* __restrict__ gwhh,
                            const float* __restrict__ lwih, const float* __restrict__ lwhh,
                            const float* __restrict__ w2, const float* __restrict__ b2) {
    int t = blockIdx.x * 256 + threadIdx.x;
    if (t < FIN * DIM) { int i = t / DIM, o = t % DIM; g_w0T[t] = w0[o * FIN + i]; }
    if (t < 11 * HID)  { int i = t / HID, j = t % HID; g_w1T[t] = w1[j * 11 + i]; }
    if (t < DIM * 96)  { int i = t / 96,  r = t % 96;  g_wihT[t] = gwih[r * DIM + i]; g_whhT[t] = gwhh[r * DIM + i]; }
    if (t < 64 * 128)  { int i = t / 128, r = t % 128; g_lwihT[t] = lwih[r * 64 + i]; }
    if (t < DIM * 128) { int i = t / 128, r = t % 128; g_lwhhT[t] = lwhh[r * DIM + i]; }
    if (t < NOUT) { int corig = (t & 31) * 32 + (t >> 5); g_b2p[t] = b2[corig]; }
    if (t < NOUT * HID) {
        int cp = t / HID, k = t % HID;
        int corig = (cp & 31) * 32 + (cp >> 5);      // cp = o*32+i holds column i*32+o
        g_w2b[t] = __float2half(w2[corig * HID + k]);
    }
}

__global__ void zero_cnt_kernel() {
    int i = blockIdx.x * 256 + threadIdx.x;
    if (i < NN) g_cnt[i] = 0;
}
__global__ void deg_kernel(const int* __restrict__ ei) {
    int e = blockIdx.x * 256 + threadIdx.x;
    if (e < NE) atomicAdd(&g_cnt[ei[NE + e]], 1);
}

// ---------------- CSR scan (exclusive prefix of cnt -> roff) ----------------
__global__ void scan1_kernel() {
    __shared__ int s[256];
    int i = blockIdx.x * 256 + threadIdx.x;
    int v = (i < NN) ? g_cnt[i] : 0;
    s[threadIdx.x] = v;
    __syncthreads();
#pragma unroll
    for (int d = 1; d < 256; d <<= 1) {
        int t = (threadIdx.x >= d) ? s[threadIdx.x - d] : 0;
        __syncthreads();
        s[threadIdx.x] += t;
        __syncthreads();
    }
    if (i < NN) g_roff[i] = s[threadIdx.x] - v;   // block-local exclusive
    if (threadIdx.x == 255) g_bsum[blockIdx.x] = s[255];
}
__global__ void scan2_kernel() {   // 1 block, 512 threads
    __shared__ int s[512];
    int v = (threadIdx.x < NBLK) ? g_bsum[threadIdx.x] : 0;
    s[threadIdx.x] = v;
    __syncthreads();
#pragma unroll
    for (int d = 1; d < 512; d <<= 1) {
        int t = (threadIdx.x >= d) ? s[threadIdx.x - d] : 0;
        __syncthreads();
        s[threadIdx.x] += t;
        __syncthreads();
    }
    if (threadIdx.x < NBLK) g_bscan[threadIdx.x] = s[threadIdx.x] - v;
}
__global__ void scan3_kernel() {
    int i = blockIdx.x * 256 + threadIdx.x;
    if (i < NN) { g_roff[i] += g_bscan[i / 256]; g_cnt[i] = 0; }
    if (i == 0) g_roff[NN] = NE;
}
// scatter edges into CSR slots; pad perm beyond NE
__global__ void scatter_kernel(const int* __restrict__ ei) {
    int e = blockIdx.x * 256 + threadIdx.x;
    if (e >= MPAD) return;
    if (e < NE) {
        int d = ei[NE + e];
        int pos = g_roff[d] + atomicAdd(&g_cnt[d], 1);
        g_perm[pos] = e;
        g_psrc[pos] = ei[e];
    } else {
        g_perm[e] = -1;
    }
}

__global__ void goff_kernel(const int* __restrict__ gidx) {
    int g = blockIdx.x * 256 + threadIdx.x;
    if (g > NB) return;
    int lo = 0, hi = NN;
    while (lo < hi) { int mid = (lo + hi) >> 1; if (gidx[mid] < g) lo = mid + 1; else hi = mid; }
    g_goff[g] = lo;
}

// ---------------- lin0: xa = relu(nf @ W0^T + b) ----------------
__global__ void lin0_kernel(const float* __restrict__ nf, const float* __restrict__ b) {
    int warp = threadIdx.x >> 5;
    int node = blockIdx.x * 8 + warp;
    int o = threadIdx.x & 31;
    __shared__ float sf[8][FIN + 1];
    int base = blockIdx.x * 8;
    for (int idx = threadIdx.x; idx < 8 * FIN; idx += 256) {
        int nn = base + idx / FIN;
        sf[idx / FIN][idx % FIN] = (nn < NN) ? nf[(size_t)nn * FIN + idx % FIN] : 0.f;
    }
    __syncthreads();
    if (node >= NN) return;
    float acc = b[o];
#pragma unroll
    for (int i = 0; i < FIN; i++) acc = fmaf(sf[warp][i], g_w0T[i * DIM + o], acc);
    g_xa[node * DIM + o] = fmaxf(acc, 0.f);
}

// ---- fused GEMM: per CTA of 128 CSR slots ----
#define SM_A     0
#define SM_B     32768
#define SM_CSTG  65536
#define SM_SEF   65536           // 128 x 12 floats
#define SM_W1T   (65536 + 6144)
#define SM_B1    (65536 + 6144 + 5632)
#define SM_BIAS  100352          // 1024 floats
#define SM_PERM  104448          // 128 ints
#define SMEM_GEMM_TOTAL 104960
#define CSTRIDE 272

__device__ __forceinline__ void mma_fp16(float* c, const uint32_t* a, uint32_t b0, uint32_t b1) {
    asm volatile(
        "mma.sync.aligned.m16n8k16.row.col.f32.f16.f16.f32 "
        "{%0,%1,%2,%3}, {%4,%5,%6,%7}, {%8,%9}, {%0,%1,%2,%3};"
        : "+f"(c[0]), "+f"(c[1]), "+f"(c[2]), "+f"(c[3])
        : "r"(a[0]), "r"(a[1]), "r"(a[2]), "r"(a[3]), "r"(b0), "r"(b1));
}

__global__ void __launch_bounds__(256) gemm_fused_kernel(const float* __restrict__ ef,
                                                         const float* __restrict__ b1) {
    extern __shared__ __align__(16) char smem[];
    uint32_t sbase = smem_u32(smem);
    float* sef   = (float*)(smem + SM_SEF);
    float* sw1t  = (float*)(smem + SM_W1T);
    float* sb1   = (float*)(smem + SM_B1);
    float* sbias = (float*)(smem + SM_BIAS);
    int*   sperm = (int*)(smem + SM_PERM);
    int tid = threadIdx.x, lane = tid & 31, wid = tid >> 5;
    int e0 = blockIdx.x * 128;

    // ---- prologue loads ----
    if (tid < 128) sperm[tid] = g_perm[e0 + tid];
    for (int idx = tid; idx < 11 * HID; idx += 256) sw1t[idx] = g_w1T[idx];
    if (tid < 128) sb1[tid] = b1[tid];
#pragma unroll
    for (int l = 0; l < 4; l++) sbias[tid + l * 256] = g_b2p[tid + l * 256];
    __syncthreads();
    for (int idx = tid; idx < 128 * 11; idx += 256) {
        int r = idx / 11, i = idx % 11;
        int ep = sperm[r];
        sef[r * 12 + i] = (ep >= 0) ? ef[(size_t)ep * 11 + i] : 0.f;
    }
    __syncthreads();

    // ---- build A tile: hw = relu(ef @ W1^T + b1), fp16, xor-swizzled ----
#pragma unroll
    for (int ci = 0; ci < 8; ci++) {
        int cidx = tid + ci * 256;
        int row = cidx >> 4, c = cidx & 15;
        int k0 = c * 8;
        float v[8];
#pragma unroll
        for (int j = 0; j < 8; j++) v[j] = sb1[k0 + j];
#pragma unroll
        for (int i = 0; i < 11; i++) {
            float e_ = sef[row * 12 + i];
#pragma unroll
            for (int j = 0; j < 8; j++) v[j] = fmaf(e_, sw1t[i * HID + k0 + j], v[j]);
        }
        uint32_t p[4];
#pragma unroll
        for (int j = 0; j < 4; j++) {
            __half2 h = __floats2half2_rn(fmaxf(v[2 * j], 0.f), fmaxf(v[2 * j + 1], 0.f));
            p[j] = *(uint32_t*)&h;
        }
        int cs = (c & 8) | ((c ^ row) & 7);
        *(uint4*)(smem + SM_A + row * 256 + cs * 16) = make_uint4(p[0], p[1], p[2], p[3]);
    }
    __syncthreads();

    int wm = (wid & 3) * 32;
    int wn = (wid >> 2) * 64;

    for (int nb = 0; nb < 8; nb++) {
        const uint4* gB = (const uint4*)(g_w2b + (size_t)(nb * 128) * HID);
#pragma unroll
        for (int it = 0; it < 8; it++) {
            int idx = tid + it * 256;
            int row = idx >> 4, c = idx & 15;
            uint4 v = gB[idx];
            int cs = (c & 8) | ((c ^ row) & 7);
            *(uint4*)(smem + SM_B + row * 256 + cs * 16) = v;
        }
        __syncthreads();

        float acc[2][8][4];
#pragma unroll
        for (int mb = 0; mb < 2; mb++)
#pragma unroll
            for (int nbb = 0; nbb < 8; nbb++)
#pragma unroll
                for (int q = 0; q < 4; q++) acc[mb][nbb][q] = 0.f;

#pragma unroll
        for (int ks = 0; ks < 8; ks++) {
            int ck0 = ks * 2;
            uint32_t a[2][4], b[4][4];
#pragma unroll
            for (int mb = 0; mb < 2; mb++) {
                int row = wm + mb * 16 + (lane & 7) + ((lane >> 3) & 1) * 8;
                int ck = ck0 + (lane >> 4);
                int cs = (ck & 8) | ((ck ^ row) & 7);
                uint32_t addr = sbase + SM_A + row * 256 + cs * 16;
                asm volatile("ldmatrix.sync.aligned.m8n8.x4.shared.b16 {%0,%1,%2,%3}, [%4];"
                             : "=r"(a[mb][0]), "=r"(a[mb][1]), "=r"(a[mb][2]), "=r"(a[mb][3])
                             : "r"(addr));
            }
#pragma unroll
            for (int nb4 = 0; nb4 < 4; nb4++) {
                int t = lane >> 3, r = lane & 7;
                int n = wn + nb4 * 16 + r + (t >> 1) * 8;
                int ck = ck0 + (t & 1);
                int cs = (ck & 8) | ((ck ^ n) & 7);
                uint32_t addr = sbase + SM_B + n * 256 + cs * 16;
                asm volatile("ldmatrix.sync.aligned.m8n8.x4.shared.b16 {%0,%1,%2,%3}, [%4];"
                             : "=r"(b[nb4][0]), "=r"(b[nb4][1]), "=r"(b[nb4][2]), "=r"(b[nb4][3])
                             : "r"(addr));
            }
#pragma unroll
            for (int mb = 0; mb < 2; mb++)
#pragma unroll
                for (int nbb = 0; nbb < 8; nbb++)
                    mma_fp16(acc[mb][nbb], a[mb], b[nbb >> 1][(nbb & 1) * 2], b[nbb >> 1][(nbb & 1) * 2 + 1]);
        }
        __syncthreads();

        int g = lane >> 2, tg = lane & 3;
#pragma unroll
        for (int mb = 0; mb < 2; mb++)
#pragma unroll
            for (int nbb = 0; nbb < 8; nbb++) {
                int rowl = wm + mb * 16 + g;
                int nl = wn + nbb * 8 + tg * 2;
                float bb0 = sbias[nb * 128 + nl], bb1 = sbias[nb * 128 + nl + 1];
                float* c = acc[mb][nbb];
                __half2 p0 = __floats2half2_rn(c[0] + bb0, c[1] + bb1);
                __half2 p1 = __floats2half2_rn(c[2] + bb0, c[3] + bb1);
                *(uint32_t*)(smem + SM_CSTG + rowl * CSTRIDE + nl * 2) = *(uint32_t*)&p0;
                *(uint32_t*)(smem + SM_CSTG + (rowl + 8) * CSTRIDE + nl * 2) = *(uint32_t*)&p1;
            }
        __syncthreads();

        __half* dst = g_ewb + (size_t)e0 * NOUT + nb * 128;
#pragma unroll
        for (int it = 0; it < 8; it++) {
            int idx = tid + it * 256;
            int row = idx >> 4, c = idx & 15;
            uint4 v = *(const uint4*)(smem + SM_CSTG + row * CSTRIDE + c * 16);
            *(uint4*)(dst + (size_t)row * NOUT + c * 8) = v;
        }
        __syncthreads();
    }
}

// ---------------- fused NNConv + scatter-mean + ReLU + GRU: one warp per node ----------------
__global__ void __launch_bounds__(256) convgru_kernel(int dir, const float* __restrict__ cbias,
                                                      const float* __restrict__ bih,
                                                      const float* __restrict__ bhh) {
    const float* __restrict__ xin = dir ? g_xb : g_xa;
    float* __restrict__ xout = dir ? g_xa : g_xb;
    __shared__ float swih[3072], swhh[3072], scb[32], sbih[96], sbhh[96];
    int tid = threadIdx.x;
    for (int idx = tid; idx < 3072; idx += 256) { swih[idx] = g_wihT[idx]; swhh[idx] = g_whhT[idx]; }
    if (tid < 32) scb[tid] = cbias[tid];
    if (tid < 96) { sbih[tid] = bih[tid]; sbhh[tid] = bhh[tid]; }
    __syncthreads();

    int warp = tid >> 5, o = tid & 31;
    int n = blockIdx.x * 8 + warp;
    if (n >= NN) return;
    int js = g_roff[n], je = g_roff[n + 1];

    float msg = 0.f;
    for (int j = js; j < je; j++) {
        int s = g_psrc[j];
        float xv = xin[s * DIM + o];
        const uint4* w = (const uint4*)(g_ewb + (size_t)j * NOUT + o * 32);
        uint4 w0 = w[0], w1 = w[1], w2 = w[2], w3 = w[3];
        uint32_t ws[16] = {w0.x, w0.y, w0.z, w0.w, w1.x, w1.y, w1.z, w1.w,
                           w2.x, w2.y, w2.z, w2.w, w3.x, w3.y, w3.z, w3.w};
        float acc = 0.f;
#pragma unroll
        for (int i = 0; i < 16; i++) {
            float2 wp = __half22float2(*(__half2*)&ws[i]);
            float x0 = __shfl_sync(0xffffffffu, xv, 2 * i);
            float x1 = __shfl_sync(0xffffffffu, xv, 2 * i + 1);
            acc = fmaf(x0, wp.x, fmaf(x1, wp.y, acc));
        }
        msg += acc;
    }
    int deg = je - js;
    float m = fmaxf((deg > 0 ? msg / (float)deg : 0.f) + scb[o], 0.f);
    float h = xin[n * DIM + o];

    float gir = sbih[o], giz = sbih[32 + o], gin = sbih[64 + o];
    float ghr = sbhh[o], ghz = sbhh[32 + o], ghn = sbhh[64 + o];
#pragma unroll
    for (int i = 0; i < DIM; i++) {
        float mi = __shfl_sync(0xffffffffu, m, i);
        float hi = __shfl_sync(0xffffffffu, h, i);
        gir = fmaf(mi, swih[i * 96 + o], gir);
        giz = fmaf(mi, swih[i * 96 + 32 + o], giz);
        gin = fmaf(mi, swih[i * 96 + 64 + o], gin);
        ghr = fmaf(hi, swhh[i * 96 + o], ghr);
        ghz = fmaf(hi, swhh[i * 96 + 32 + o], ghz);
        ghn = fmaf(hi, swhh[i * 96 + 64 + o], ghn);
    }
    float r = 1.f / (1.f + expf(-(gir + ghr)));
    float z = 1.f / (1.f + expf(-(giz + ghz)));
    float nv = tanhf(gin + r * ghn);
    xout[n * DIM + o] = (1.f - z) * nv + z * h;
}

__global__ void zero_s2s_kernel() {
    int i = blockIdx.x * 256 + threadIdx.x;
    if (i < NB * DIM) { g_h2[i] = 0.f; g_c2[i] = 0.f; }
    if (i < NB * 2 * DIM) g_qstar[i] = 0.f;
}

// ---------------- Set2Set LSTM cell ----------------
__global__ void lstm_kernel(const float* __restrict__ bih, const float* __restrict__ bhh) {
    int warp = threadIdx.x >> 5;
    int b = blockIdx.x * 8 + warp;
    int o = threadIdx.x & 31;
    __shared__ float sq[8][64], shh[8][DIM];
    if (b < NB) {
        sq[warp][o]      = g_qstar[b * 64 + o];
        sq[warp][32 + o] = g_qstar[b * 64 + 32 + o];
        shh[warp][o]     = g_h2[b * DIM + o];
    }
    __syncthreads();
    if (b >= NB) return;
    float gi = bih[o] + bhh[o];
    float gf = bih[32 + o] + bhh[32 + o];
    float gg = bih[64 + o] + bhh[64 + o];
    float go = bih[96 + o] + bhh[96 + o];
#pragma unroll
    for (int i = 0; i < 64; i++) {
        float v = sq[warp][i];
        gi = fmaf(v, g_lwihT[i * 128 + o], gi);
        gf = fmaf(v, g_lwihT[i * 128 + 32 + o], gf);
        gg = fmaf(v, g_lwihT[i * 128 + 64 + o], gg);
        go = fmaf(v, g_lwihT[i * 128 + 96 + o], go);
    }
#pragma unroll
    for (int i = 0; i < DIM; i++) {
        float v = shh[warp][i];
        gi = fmaf(v, g_lwhhT[i * 128 + o], gi);
        gf = fmaf(v, g_lwhhT[i * 128 + 32 + o], gf);
        gg = fmaf(v, g_lwhhT[i * 128 + 64 + o], gg);
        go = fmaf(v, g_lwhhT[i * 128 + 96 + o], go);
    }
    float si = 1.f / (1.f + expf(-gi));
    float sf = 1.f / (1.f + expf(-gf));
    float so = 1.f / (1.f + expf(-go));
    float cc = sf * g_c2[b * DIM + o] + si * tanhf(gg);
    g_c2[b * DIM + o] = cc;
    g_h2[b * DIM + o] = so * tanhf(cc);
}

// ---------------- Set2Set attention: one block per graph (reads g_xb) ----------------
__global__ void attn_kernel() {
    int g = blockIdx.x;
    int s = g_goff[g], e = g_goff[g + 1];
    int lane = threadIdx.x & 31, w = threadIdx.x >> 5;
    __shared__ float q[DIM];
    __shared__ float red[4];
    __shared__ float sr[4][DIM];
    __shared__ float sd[4];
    if (threadIdx.x < DIM) q[threadIdx.x] = g_h2[g * DIM + threadIdx.x];
    __syncthreads();
    float mx = -INFINITY;
    for (int n = s + w; n < e; n += 4) {
        float v = g_xb[n * DIM + lane] * q[lane];
#pragma unroll
        for (int off = 16; off; off >>= 1) v += __shfl_xor_sync(0xffffffffu, v, off);
        mx = fmaxf(mx, v);
    }
    if (lane == 0) red[w] = mx;
    __syncthreads();
    mx = fmaxf(fmaxf(red[0], red[1]), fmaxf(red[2], red[3]));
    float denom = 0.f, racc = 0.f;
    for (int n = s + w; n < e; n += 4) {
        float xo = g_xb[n * DIM + lane];
        float v = xo * q[lane];
#pragma unroll
        for (int off = 16; off; off >>= 1) v += __shfl_xor_sync(0xffffffffu, v, off);
        float ex = __expf(v - mx);
        denom += ex;
        racc = fmaf(ex, xo, racc);
    }
    sr[w][lane] = racc;
    if (lane == 0) sd[w] = denom;
    __syncthreads();
    if (w == 0) {
        float r = sr[0][lane] + sr[1][lane] + sr[2][lane] + sr[3][lane];
        float d = sd[0] + sd[1] + sd[2] + sd[3];
        r = (d > 0.f) ? r / d : 0.f;
        g_qstar[g * 64 + lane] = q[lane];
        g_qstar[g * 64 + 32 + lane] = r;
    }
}

// ---------------- writeout: [pooled (2000x64), out (100000x32)] ----------------
__global__ void writeout_kernel(float* __restrict__ out) {
    int i = blockIdx.x * 256 + threadIdx.x;
    if (i >= NB * 64 + NN * DIM) return;
    out[i] = (i < NB * 64) ? g_qstar[i] : g_xb[i - NB * 64];
}

// ---------------- launch ----------------
extern "C" void kernel_launch(void* const* d_in, const int* in_sizes, int n_in,
                              void* d_out, int out_size) {
    const float* nf        = (const float*)d_in[0];
    const float* ef        = (const float*)d_in[1];
    const float* lin0_w    = (const float*)d_in[2];
    const float* lin0_b    = (const float*)d_in[3];
    const float* nn_w1     = (const float*)d_in[4];
    const float* nn_b1     = (const float*)d_in[5];
    const float* nn_w2     = (const float*)d_in[6];
    const float* nn_b2     = (const float*)d_in[7];
    const float* conv_bias = (const float*)d_in[8];
    const float* gru_wih   = (const float*)d_in[9];
    const float* gru_whh   = (const float*)d_in[10];
    const float* gru_bih   = (const float*)d_in[11];
    const float* gru_bhh   = (const float*)d_in[12];
    const float* lstm_wih  = (const float*)d_in[13];
    const float* lstm_whh  = (const float*)d_in[14];
    const float* lstm_bih  = (const float*)d_in[15];
    const float* lstm_bhh  = (const float*)d_in[16];
    const int*   ei        = (const int*)d_in[17];
    const int*   gidx      = (const int*)d_in[18];

    static int smem_set = 0;
    if (!smem_set) {
        cudaFuncSetAttribute(gemm_fused_kernel, cudaFuncAttributeMaxDynamicSharedMemorySize,
                             SMEM_GEMM_TOTAL);
        smem_set = 1;
    }

    prep_kernel<<<512, 256>>>(lin0_w, nn_w1, gru_wih, gru_whh, lstm_wih, lstm_whh, nn_w2, nn_b2);
    zero_cnt_kernel<<<NBLK, 256>>>();
    deg_kernel<<<(NE + 255) / 256, 256>>>(ei);
    scan1_kernel<<<NBLK, 256>>>();
    scan2_kernel<<<1, 512>>>();
    scan3_kernel<<<NBLK, 256>>>();
    scatter_kernel<<<MPAD / 256, 256>>>(ei);
    goff_kernel<<<8, 256>>>(gidx);
    lin0_kernel<<<NN / 8, 256>>>(nf, lin0_b);
    gemm_fused_kernel<<<MPAD / 128, 256, SMEM_GEMM_TOTAL>>>(ef, nn_b1);

    for (int t = 0; t < 3; t++)
        convgru_kernel<<<NN / 8, 256>>>(t & 1, conv_bias, gru_bih, gru_bhh);

    zero_s2s_kernel<<<(NB * 2 * DIM + 255) / 256, 256>>>();
    for (int s = 0; s < 3; s++) {
        lstm_kernel<<<NB / 8, 256>>>(lstm_bih, lstm_bhh);
        attn_kernel<<<NB, 128>>>();
    }
    writeout_kernel<<<(NB * 64 + NN * DIM + 255) / 256, 256>>>((float*)d_out);
}

// round 7
// speedup vs baseline: 2.4949x; 1.0764x over previous
#include <cuda_runtime.h>
#include <cuda_fp16.h>
#include <math.h>
#include <stdint.h>

#define NN   100000
#define NE   250000
#define NB   2000
#define FIN  75
#define DIM  32
#define HID  128
#define NOUT 1024           // DIM*DIM
#define MPAD 250112         // 1954 * 128

// ---------------- scratch (static __device__, no allocation) ----------------
__device__ __align__(16) __half g_ewb[(size_t)MPAD * NOUT];  // edge weights fp16, [o][i] per edge
__device__ __align__(16) __half g_w2b[NOUT * HID];           // W2 fp16, column-permuted (c' = o*32+i)
__device__ float g_b2p[NOUT];                                // b2 permuted
__device__ float g_x[NN * DIM];                 // node state
__device__ float g_acc[NN * DIM];               // conv scatter accumulator
__device__ int   g_cnt[NN];                     // in-degree
__device__ int   g_goff[NB + 1];                // graph offsets (graph_index is sorted)
__device__ float g_h2[NB * DIM];                // set2set LSTM h
__device__ float g_c2[NB * DIM];                // set2set LSTM c
__device__ float g_qstar[NB * 2 * DIM];         // set2set q_star
// transposed weights
__device__ float g_w0T[FIN * DIM];
__device__ float g_w1T[11 * HID];
__device__ float g_wihT[DIM * 96];
__device__ float g_whhT[DIM * 96];
__device__ float g_lwihT[64 * 128];
__device__ float g_lwhhT[DIM * 128];

__device__ __forceinline__ uint32_t smem_u32(const void* p) {
    uint32_t a;
    asm("{ .reg .u64 t; cvta.to.shared.u64 t, %1; cvt.u32.u64 %0, t; }" : "=r"(a) : "l"(p));
    return a;
}

// ---------------- prep: transposes + fp16 W2 with column permutation + zero cnt ----------------
__global__ void prep_kernel(const float* __restrict__ w0, const float* __restrict__ w1,
                            const float* __restrict__ gwih, const float* __restrict__ gwhh,
                            const float* __restrict__ lwih, const float* __restrict__ lwhh,
                            const float* __restrict__ w2, const float* __restrict__ b2) {
    int t = blockIdx.x * 256 + threadIdx.x;
    if (t < FIN * DIM) { int i = t / DIM, o = t % DIM; g_w0T[t] = w0[o * FIN + i]; }
    if (t < 11 * HID)  { int i = t / HID, j = t % HID; g_w1T[t] = w1[j * 11 + i]; }
    if (t < DIM * 96)  { int i = t / 96,  r = t % 96;  g_wihT[t] = gwih[r * DIM + i]; g_whhT[t] = gwhh[r * DIM + i]; }
    if (t < 64 * 128)  { int i = t / 128, r = t % 128; g_lwihT[t] = lwih[r * 64 + i]; }
    if (t < DIM * 128) { int i = t / 128, r = t % 128; g_lwhhT[t] = lwhh[r * DIM + i]; }
    if (t < NOUT) { int corig = (t & 31) * 32 + (t >> 5); g_b2p[t] = b2[corig]; }
    if (t < NOUT * HID) {
        int cp = t / HID, k = t % HID;
        int corig = (cp & 31) * 32 + (cp >> 5);      // cp = o*32+i holds original column i*32+o
        g_w2b[t] = __float2half(w2[corig * HID + k]);
    }
}

__global__ void zero_cnt_kernel() {
    int i = blockIdx.x * 256 + threadIdx.x;
    if (i < NN) g_cnt[i] = 0;
}
__global__ void deg_kernel(const int* __restrict__ ei) {
    int e = blockIdx.x * 256 + threadIdx.x;
    if (e < NE) atomicAdd(&g_cnt[ei[NE + e]], 1);
}

__global__ void goff_kernel(const int* __restrict__ gidx) {
    int g = blockIdx.x * 256 + threadIdx.x;
    if (g > NB) return;
    int lo = 0, hi = NN;
    while (lo < hi) { int mid = (lo + hi) >> 1; if (gidx[mid] < g) lo = mid + 1; else hi = mid; }
    g_goff[g] = lo;
}

// ---------------- lin0: x = relu(nf @ W0^T + b) ----------------
__global__ void lin0_kernel(const float* __restrict__ nf, const float* __restrict__ b) {
    int warp = threadIdx.x >> 5;
    int node = blockIdx.x * 8 + warp;
    int o = threadIdx.x & 31;
    __shared__ float sf[8][FIN + 1];
    int base = blockIdx.x * 8;
    for (int idx = threadIdx.x; idx < 8 * FIN; idx += 256) {
        int nn = base + idx / FIN;
        sf[idx / FIN][idx % FIN] = (nn < NN) ? nf[(size_t)nn * FIN + idx % FIN] : 0.f;
    }
    __syncthreads();
    if (node >= NN) return;
    float acc = b[o];
#pragma unroll
    for (int i = 0; i < FIN; i++) acc = fmaf(sf[warp][i], g_w0T[i * DIM + o], acc);
    g_x[node * DIM + o] = fmaxf(acc, 0.f);
}

// ---- fused GEMM: per CTA of 128 edges; hw built in-smem, loop over 8 N-slabs ----
#define SM_A     0
#define SM_B     32768
#define SM_CSTG  65536
#define SM_SEF   65536           // 128 x 12 floats
#define SM_W1T   (65536 + 6144)
#define SM_B1    (65536 + 6144 + 5632)
#define SM_BIAS  100352          // 1024 floats
#define SMEM_GEMM_TOTAL 104448
#define CSTRIDE 272

__device__ __forceinline__ void mma_fp16(float* c, const uint32_t* a, uint32_t b0, uint32_t b1) {
    asm volatile(
        "mma.sync.aligned.m16n8k16.row.col.f32.f16.f16.f32 "
        "{%0,%1,%2,%3}, {%4,%5,%6,%7}, {%8,%9}, {%0,%1,%2,%3};"
        : "+f"(c[0]), "+f"(c[1]), "+f"(c[2]), "+f"(c[3])
        : "r"(a[0]), "r"(a[1]), "r"(a[2]), "r"(a[3]), "r"(b0), "r"(b1));
}

__global__ void __launch_bounds__(256) gemm_fused_kernel(const float* __restrict__ ef,
                                                         const float* __restrict__ b1) {
    extern __shared__ __align__(16) char smem[];
    uint32_t sbase = smem_u32(smem);
    float* sef   = (float*)(smem + SM_SEF);
    float* sw1t  = (float*)(smem + SM_W1T);
    float* sb1   = (float*)(smem + SM_B1);
    float* sbias = (float*)(smem + SM_BIAS);
    int tid = threadIdx.x, lane = tid & 31, wid = tid >> 5;
    int e0 = blockIdx.x * 128;

    // ---- prologue loads ----
    for (int idx = tid; idx < 128 * 11; idx += 256) {
        int r = idx / 11, i = idx % 11;
        int e = e0 + r;
        sef[r * 12 + i] = (e < NE) ? ef[(size_t)e * 11 + i] : 0.f;
    }
    for (int idx = tid; idx < 11 * HID; idx += 256) sw1t[idx] = g_w1T[idx];
    if (tid < 128) sb1[tid] = b1[tid];
#pragma unroll
    for (int l = 0; l < 4; l++) sbias[tid + l * 256] = g_b2p[tid + l * 256];
    __syncthreads();

    // ---- build A tile: hw = relu(ef @ W1^T + b1), fp16, xor-swizzled ----
#pragma unroll
    for (int ci = 0; ci < 8; ci++) {
        int cidx = tid + ci * 256;
        int row = cidx >> 4, c = cidx & 15;
        int k0 = c * 8;
        float v[8];
#pragma unroll
        for (int j = 0; j < 8; j++) v[j] = sb1[k0 + j];
#pragma unroll
        for (int i = 0; i < 11; i++) {
            float e_ = sef[row * 12 + i];
#pragma unroll
            for (int j = 0; j < 8; j++) v[j] = fmaf(e_, sw1t[i * HID + k0 + j], v[j]);
        }
        uint32_t p[4];
#pragma unroll
        for (int j = 0; j < 4; j++) {
            __half2 h = __floats2half2_rn(fmaxf(v[2 * j], 0.f), fmaxf(v[2 * j + 1], 0.f));
            p[j] = *(uint32_t*)&h;
        }
        int cs = (c & 8) | ((c ^ row) & 7);
        *(uint4*)(smem + SM_A + row * 256 + cs * 16) = make_uint4(p[0], p[1], p[2], p[3]);
    }
    __syncthreads();

    int wm = (wid & 3) * 32;
    int wn = (wid >> 2) * 64;

    for (int nb = 0; nb < 8; nb++) {
        const uint4* gB = (const uint4*)(g_w2b + (size_t)(nb * 128) * HID);
#pragma unroll
        for (int it = 0; it < 8; it++) {
            int idx = tid + it * 256;
            int row = idx >> 4, c = idx & 15;
            uint4 v = gB[idx];
            int cs = (c & 8) | ((c ^ row) & 7);
            *(uint4*)(smem + SM_B + row * 256 + cs * 16) = v;
        }
        __syncthreads();

        float acc[2][8][4];
#pragma unroll
        for (int mb = 0; mb < 2; mb++)
#pragma unroll
            for (int nbb = 0; nbb < 8; nbb++)
#pragma unroll
                for (int q = 0; q < 4; q++) acc[mb][nbb][q] = 0.f;

#pragma unroll
        for (int ks = 0; ks < 8; ks++) {
            int ck0 = ks * 2;
            uint32_t a[2][4], b[4][4];
#pragma unroll
            for (int mb = 0; mb < 2; mb++) {
                int row = wm + mb * 16 + (lane & 7) + ((lane >> 3) & 1) * 8;
                int ck = ck0 + (lane >> 4);
                int cs = (ck & 8) | ((ck ^ row) & 7);
                uint32_t addr = sbase + SM_A + row * 256 + cs * 16;
                asm volatile("ldmatrix.sync.aligned.m8n8.x4.shared.b16 {%0,%1,%2,%3}, [%4];"
                             : "=r"(a[mb][0]), "=r"(a[mb][1]), "=r"(a[mb][2]), "=r"(a[mb][3])
                             : "r"(addr));
            }
#pragma unroll
            for (int nb4 = 0; nb4 < 4; nb4++) {
                int t = lane >> 3, r = lane & 7;
                int n = wn + nb4 * 16 + r + (t >> 1) * 8;
                int ck = ck0 + (t & 1);
                int cs = (ck & 8) | ((ck ^ n) & 7);
                uint32_t addr = sbase + SM_B + n * 256 + cs * 16;
                asm volatile("ldmatrix.sync.aligned.m8n8.x4.shared.b16 {%0,%1,%2,%3}, [%4];"
                             : "=r"(b[nb4][0]), "=r"(b[nb4][1]), "=r"(b[nb4][2]), "=r"(b[nb4][3])
                             : "r"(addr));
            }
#pragma unroll
            for (int mb = 0; mb < 2; mb++)
#pragma unroll
                for (int nbb = 0; nbb < 8; nbb++)
                    mma_fp16(acc[mb][nbb], a[mb], b[nbb >> 1][(nbb & 1) * 2], b[nbb >> 1][(nbb & 1) * 2 + 1]);
        }
        __syncthreads();

        int g = lane >> 2, tg = lane & 3;
#pragma unroll
        for (int mb = 0; mb < 2; mb++)
#pragma unroll
            for (int nbb = 0; nbb < 8; nbb++) {
                int rowl = wm + mb * 16 + g;
                int nl = wn + nbb * 8 + tg * 2;
                float bb0 = sbias[nb * 128 + nl], bb1 = sbias[nb * 128 + nl + 1];
                float* c = acc[mb][nbb];
                __half2 p0 = __floats2half2_rn(c[0] + bb0, c[1] + bb1);
                __half2 p1 = __floats2half2_rn(c[2] + bb0, c[3] + bb1);
                *(uint32_t*)(smem + SM_CSTG + rowl * CSTRIDE + nl * 2) = *(uint32_t*)&p0;
                *(uint32_t*)(smem + SM_CSTG + (rowl + 8) * CSTRIDE + nl * 2) = *(uint32_t*)&p1;
            }
        __syncthreads();

        __half* dst = g_ewb + (size_t)e0 * NOUT + nb * 128;
#pragma unroll
        for (int it = 0; it < 8; it++) {
            int idx = tid + it * 256;
            int row = idx >> 4, c = idx & 15;
            uint4 v = *(const uint4*)(smem + SM_CSTG + row * CSTRIDE + c * 16);
            *(uint4*)(dst + (size_t)row * NOUT + c * 8) = v;
        }
        __syncthreads();
    }
}

__global__ void zero_acc_kernel() {
    int i = blockIdx.x * 256 + threadIdx.x;
    if (i < NN * DIM) g_acc[i] = 0.f;
}

// ---------------- NNConv: warp per edge, lane = output channel, [o][i] vectorized loads ----------------
__global__ void conv_kernel(const int* __restrict__ ei) {
    int e = blockIdx.x * 8 + (threadIdx.x >> 5);
    if (e >= NE) return;
    int o = threadIdx.x & 31;
    int src = ei[e];
    int dst = ei[NE + e];
    float xv = g_x[src * DIM + o];
    const uint4* w = (const uint4*)(g_ewb + (size_t)e * NOUT + o * 32);
    uint4 w0 = w[0], w1 = w[1], w2 = w[2], w3 = w[3];
    uint32_t ws[16] = {w0.x, w0.y, w0.z, w0.w, w1.x, w1.y, w1.z, w1.w,
                       w2.x, w2.y, w2.z, w2.w, w3.x, w3.y, w3.z, w3.w};
    float acc = 0.f;
#pragma unroll
    for (int i = 0; i < 16; i++) {
        float2 wp = __half22float2(*(__half2*)&ws[i]);
        float x0 = __shfl_sync(0xffffffffu, xv, 2 * i);
        float x1 = __shfl_sync(0xffffffffu, xv, 2 * i + 1);
        acc = fmaf(x0, wp.x, fmaf(x1, wp.y, acc));
    }
    atomicAdd(&g_acc[dst * DIM + o], acc);
}

// ---------------- scatter-mean + relu + GRU (in-place on g_x) ----------------
__global__ void gru_kernel(const float* __restrict__ cbias, const float* __restrict__ bih,
                           const float* __restrict__ bhh) {
    int warp = threadIdx.x >> 5;
    int node = blockIdx.x * 8 + warp;
    int o = threadIdx.x & 31;
    __shared__ float sm[8][DIM], sh[8][DIM];
    if (node < NN) {
        int c = g_cnt[node]; if (c < 1) c = 1;
        sm[warp][o] = fmaxf(g_acc[node * DIM + o] / (float)c + cbias[o], 0.f);
        sh[warp][o] = g_x[node * DIM + o];
    }
    __syncthreads();
    if (node >= NN) return;
    float gir = bih[o], giz = bih[DIM + o], gin = bih[2 * DIM + o];
    float ghr = bhh[o], ghz = bhh[DIM + o], ghn = bhh[2 * DIM + o];
#pragma unroll
    for (int i = 0; i < DIM; i++) {
        float mi = sm[warp][i], hi = sh[warp][i];
        gir = fmaf(mi, g_wihT[i * 96 + o], gir);
        giz = fmaf(mi, g_wihT[i * 96 + DIM + o], giz);
        gin = fmaf(mi, g_wihT[i * 96 + 2 * DIM + o], gin);
        ghr = fmaf(hi, g_whhT[i * 96 + o], ghr);
        ghz = fmaf(hi, g_whhT[i * 96 + DIM + o], ghz);
        ghn = fmaf(hi, g_whhT[i * 96 + 2 * DIM + o], ghn);
    }
    float r = 1.f / (1.f + expf(-(gir + ghr)));
    float z = 1.f / (1.f + expf(-(giz + ghz)));
    float nv = tanhf(gin + r * ghn);
    g_x[node * DIM + o] = (1.f - z) * nv + z * sh[warp][o];
}

__global__ void zero_s2s_kernel() {
    int i = blockIdx.x * 256 + threadIdx.x;
    if (i < NB * DIM) { g_h2[i] = 0.f; g_c2[i] = 0.f; }
    if (i < NB * 2 * DIM) g_qstar[i] = 0.f;
}

// ---------------- Set2Set LSTM cell ----------------
__global__ void lstm_kernel(const float* __restrict__ bih, const float* __restrict__ bhh) {
    int warp = threadIdx.x >> 5;
    int b = blockIdx.x * 8 + warp;
    int o = threadIdx.x & 31;
    __shared__ float sq[8][64], shh[8][DIM];
    if (b < NB) {
        sq[warp][o]      = g_qstar[b * 64 + o];
        sq[warp][32 + o] = g_qstar[b * 64 + 32 + o];
        shh[warp][o]     = g_h2[b * DIM + o];
    }
    __syncthreads();
    if (b >= NB) return;
    float gi = bih[o] + bhh[o];
    float gf = bih[32 + o] + bhh[32 + o];
    float gg = bih[64 + o] + bhh[64 + o];
    float go = bih[96 + o] + bhh[96 + o];
#pragma unroll
    for (int i = 0; i < 64; i++) {
        float v = sq[warp][i];
        gi = fmaf(v, g_lwihT[i * 128 + o], gi);
        gf = fmaf(v, g_lwihT[i * 128 + 32 + o], gf);
        gg = fmaf(v, g_lwihT[i * 128 + 64 + o], gg);
        go = fmaf(v, g_lwihT[i * 128 + 96 + o], go);
    }
#pragma unroll
    for (int i = 0; i < DIM; i++) {
        float v = shh[warp][i];
        gi = fmaf(v, g_lwhhT[i * 128 + o], gi);
        gf = fmaf(v, g_lwhhT[i * 128 + 32 + o], gf);
        gg = fmaf(v, g_lwhhT[i * 128 + 64 + o], gg);
        go = fmaf(v, g_lwhhT[i * 128 + 96 + o], go);
    }
    float si = 1.f / (1.f + expf(-gi));
    float sf = 1.f / (1.f + expf(-gf));
    float so = 1.f / (1.f + expf(-go));
    float cc = sf * g_c2[b * DIM + o] + si * tanhf(gg);
    g_c2[b * DIM + o] = cc;
    g_h2[b * DIM + o] = so * tanhf(cc);
}

// ---------------- Set2Set attention: one block per graph ----------------
__global__ void attn_kernel() {
    int g = blockIdx.x;
    int s = g_goff[g], e = g_goff[g + 1];
    int lane = threadIdx.x & 31, w = threadIdx.x >> 5;
    __shared__ float q[DIM];
    __shared__ float red[4];
    __shared__ float sr[4][DIM];
    __shared__ float sd[4];
    if (threadIdx.x < DIM) q[threadIdx.x] = g_h2[g * DIM + threadIdx.x];
    __syncthreads();
    float mx = -INFINITY;
    for (int n = s + w; n < e; n += 4) {
        float v = g_x[n * DIM + lane] * q[lane];
#pragma unroll
        for (int off = 16; off; off >>= 1) v += __shfl_xor_sync(0xffffffffu, v, off);
        mx = fmaxf(mx, v);
    }
    if (lane == 0) red[w] = mx;
    __syncthreads();
    mx = fmaxf(fmaxf(red[0], red[1]), fmaxf(red[2], red[3]));
    float denom = 0.f, racc = 0.f;
    for (int n = s + w; n < e; n += 4) {
        float xo = g_x[n * DIM + lane];
        float v = xo * q[lane];
#pragma unroll
        for (int off = 16; off; off >>= 1) v += __shfl_xor_sync(0xffffffffu, v, off);
        float ex = __expf(v - mx);
        denom += ex;
        racc = fmaf(ex, xo, racc);
    }
    sr[w][lane] = racc;
    if (lane == 0) sd[w] = denom;
    __syncthreads();
    if (w == 0) {
        float r = sr[0][lane] + sr[1][lane] + sr[2][lane] + sr[3][lane];
        float d = sd[0] + sd[1] + sd[2] + sd[3];
        r = (d > 0.f) ? r / d : 0.f;
        g_qstar[g * 64 + lane] = q[lane];
        g_qstar[g * 64 + 32 + lane] = r;
    }
}

// ---------------- writeout: [pooled (2000x64), out (100000x32)] ----------------
__global__ void writeout_kernel(float* __restrict__ out) {
    int i = blockIdx.x * 256 + threadIdx.x;
    if (i >= NB * 64 + NN * DIM) return;
    out[i] = (i < NB * 64) ? g_qstar[i] : g_x[i - NB * 64];
}

// ---------------- launch ----------------
extern "C" void kernel_launch(void* const* d_in, const int* in_sizes, int n_in,
                              void* d_out, int out_size) {
    const float* nf        = (const float*)d_in[0];
    const float* ef        = (const float*)d_in[1];
    const float* lin0_w    = (const float*)d_in[2];
    const float* lin0_b    = (const float*)d_in[3];
    const float* nn_w1     = (const float*)d_in[4];
    const float* nn_b1     = (const float*)d_in[5];
    const float* nn_w2     = (const float*)d_in[6];
    const float* nn_b2     = (const float*)d_in[7];
    const float* conv_bias = (const float*)d_in[8];
    const float* gru_wih   = (const float*)d_in[9];
    const float* gru_whh   = (const float*)d_in[10];
    const float* gru_bih   = (const float*)d_in[11];
    const float* gru_bhh   = (const float*)d_in[12];
    const float* lstm_wih  = (const float*)d_in[13];
    const float* lstm_whh  = (const float*)d_in[14];
    const float* lstm_bih  = (const float*)d_in[15];
    const float* lstm_bhh  = (const float*)d_in[16];
    const int*   ei        = (const int*)d_in[17];
    const int*   gidx      = (const int*)d_in[18];

    static int smem_set = 0;
    if (!smem_set) {
        cudaFuncSetAttribute(gemm_fused_kernel, cudaFuncAttributeMaxDynamicSharedMemorySize,
                             SMEM_GEMM_TOTAL);
        smem_set = 1;
    }

    // launch order chosen so gemm_fused_kernel is launch #6 (ncu -s 5 -c 1 captures it)
    prep_kernel<<<512, 256>>>(lin0_w, nn_w1, gru_wih, gru_whh, lstm_wih, lstm_whh, nn_w2, nn_b2);
    zero_cnt_kernel<<<(NN + 255) / 256, 256>>>();
    deg_kernel<<<(NE + 255) / 256, 256>>>(ei);
    goff_kernel<<<8, 256>>>(gidx);
    lin0_kernel<<<NN / 8, 256>>>(nf, lin0_b);
    gemm_fused_kernel<<<MPAD / 128, 256, SMEM_GEMM_TOTAL>>>(ef, nn_b1);

    for (int t = 0; t < 3; t++) {
        zero_acc_kernel<<<(NN * DIM + 255) / 256, 256>>>();
        conv_kernel<<<NE / 8, 256>>>(ei);
        gru_kernel<<<NN / 8, 256>>>(conv_bias, gru_bih, gru_bhh);
    }

    zero_s2s_kernel<<<(NB * 2 * DIM + 255) / 256, 256>>>();
    for (int s = 0; s < 3; s++) {
        lstm_kernel<<<NB / 8, 256>>>(lstm_bih, lstm_bhh);
        attn_kernel<<<NB, 128>>>();
    }
    writeout_kernel<<<(NB * 64 + NN * DIM + 255) / 256, 256>>>((float*)d_out);
}